// round 5
// baseline (speedup 1.0000x reference)
#include <cuda_runtime.h>
#include <cuda_fp16.h>
#include <math.h>
#include <stdint.h>

// ---------------- problem constants ----------------
#define B_  32
#define C_  3
#define IMG_ 224
#define P_  16
#define W_  768
#define L_  12
#define H_  12
#define S_  197
#define HD_ 64
#define FF_ 3072
#define E_  512
#define NPATCH_ 196
#define BSW_ (B_*S_*W_)

// ---------------- scratch (no cudaMalloc allowed) ----------------
__device__ float g_h   [BSW_];
__device__ float g_y   [BSW_];
__device__ float g_q   [BSW_];
__device__ float g_k   [BSW_];
__device__ float g_v   [BSW_];
__device__ float g_o   [BSW_];
__device__ float g_att [B_*H_*S_*S_];
__device__ float g_ff  [B_*S_*FF_];
__device__ float g_im2col[B_*NPATCH_*W_];
__device__ float g_tok [B_*NPATCH_*W_];
__device__ float g_cls [B_*W_];
// transposed weights ([N,K], K-contiguous, for the .col B operand)
__device__ float g_wqT [L_*W_*W_];
__device__ float g_wkT [L_*W_*W_];
__device__ float g_wvT [L_*W_*W_];
__device__ float g_woT [L_*W_*W_];
__device__ float g_w1T [L_*W_*FF_];
__device__ float g_w2T [L_*FF_*W_];
__device__ float g_projT[W_*E_];

__device__ __forceinline__ float gelu_exact(float v) {
    return 0.5f * v * (1.0f + erff(v * 0.70710678118654752f));
}
__device__ __forceinline__ uint32_t smem_u32(const void* p) {
    uint32_t a;
    asm("{ .reg .u64 t; cvta.to.shared.u64 t, %1; cvt.u32.u64 %0, t; }" : "=r"(a) : "l"(p));
    return a;
}
__device__ __forceinline__ uint32_t pack_h2(float a, float b) {
    __half2 h = __floats2half2_rn(a, b);
    return *reinterpret_cast<uint32_t*>(&h);
}

#define LDSM_X4(r, addr) \
    asm volatile("ldmatrix.sync.aligned.m8n8.x4.shared.b16 {%0,%1,%2,%3}, [%4];" \
        : "=r"((r)[0]), "=r"((r)[1]), "=r"((r)[2]), "=r"((r)[3]) : "r"(addr))
#define LDSM_X2(r, addr) \
    asm volatile("ldmatrix.sync.aligned.m8n8.x2.shared.b16 {%0,%1}, [%2];" \
        : "=r"((r)[0]), "=r"((r)[1]) : "r"(addr))

// ============ fp16 HMMA GEMM: C[M,N] = A[M,K] @ Bt[N,K]^T (+bias/gelu/residual)
// Block 128x128, K-tile 32, 8 warps each 64x32 (4 mtiles m16 x 4 ntiles n8),
// fragments via ldmatrix on 80B-row-stride smem (conflict-free: 5r+c perm).
#define ASTRIDE 80
#define TILEB   (128 * ASTRIDE)   // 10240 bytes

template<int HAS_BIAS, int ACCUM, int DO_GELU>
__global__ __launch_bounds__(256)
void gemm_hmma(const float* __restrict__ A, const float* __restrict__ Bt,
               const float* __restrict__ bias, float* __restrict__ C,
               int M, int N, int K)
{
    __shared__ __align__(16) uint8_t smA[2][TILEB];
    __shared__ __align__(16) uint8_t smB[2][TILEB];

    const int t    = threadIdx.x;
    const int warp = t >> 5, lane = t & 31;
    const int m0   = blockIdx.y * 128;
    const int n0   = blockIdx.x * 128;
    const int wm   = (warp >> 2) * 64;   // 0 or 64
    const int wn   = (warp & 3) * 32;    // 0,32,64,96
    const int grp  = lane >> 2;          // 0..7
    const int idx  = lane & 3;           // 0..3

    float acc[4][4][4];
    #pragma unroll
    for (int a = 0; a < 4; a++)
        #pragma unroll
        for (int b = 0; b < 4; b++)
            #pragma unroll
            for (int c = 0; c < 4; c++) acc[a][b][c] = 0.0f;

    const int rowS = t >> 1;           // 0..127
    const int segf = (t & 1) * 16;     // float column offset (0 or 16)

    float4 ra[4], rb[4];

    auto loadRegs = [&](int k0) {
        const int gm = m0 + rowS;
        const float* pa = A + (size_t)gm * K + k0 + segf;
        #pragma unroll
        for (int i = 0; i < 4; i++)
            ra[i] = (gm < M) ? *reinterpret_cast<const float4*>(pa + i * 4)
                             : make_float4(0.f, 0.f, 0.f, 0.f);
        const float* pb = Bt + (size_t)(n0 + rowS) * K + k0 + segf;
        #pragma unroll
        for (int i = 0; i < 4; i++)
            rb[i] = *reinterpret_cast<const float4*>(pb + i * 4);
    };

    auto storeSmem = [&](int b) {
        uint8_t* pa = smA[b] + rowS * ASTRIDE + (t & 1) * 32;
        uint8_t* pb = smB[b] + rowS * ASTRIDE + (t & 1) * 32;
        #pragma unroll
        for (int i = 0; i < 4; i++) {
            uint2 ua = make_uint2(pack_h2(ra[i].x, ra[i].y), pack_h2(ra[i].z, ra[i].w));
            *reinterpret_cast<uint2*>(pa + i * 8) = ua;
            uint2 ub = make_uint2(pack_h2(rb[i].x, rb[i].y), pack_h2(rb[i].z, rb[i].w));
            *reinterpret_cast<uint2*>(pb + i * 8) = ub;
        }
    };

    // per-warp ldmatrix base offsets
    const int aoff = (wm + (lane & 15)) * ASTRIDE + (lane >> 4) * 16;
    const int boff = (wn + (lane & 7))  * ASTRIDE + ((lane >> 3) & 1) * 16;

    auto compute = [&](int b) {
        const uint32_t sa = smem_u32(smA[b]);
        const uint32_t sb = smem_u32(smB[b]);
        #pragma unroll
        for (int ks = 0; ks < 2; ks++) {
            uint32_t af[4][4], bf[4][2];
            #pragma unroll
            for (int mt = 0; mt < 4; mt++)
                LDSM_X4(af[mt], sa + aoff + mt * 16 * ASTRIDE + ks * 32);
            #pragma unroll
            for (int nt = 0; nt < 4; nt++)
                LDSM_X2(bf[nt], sb + boff + nt * 8 * ASTRIDE + ks * 32);
            #pragma unroll
            for (int mt = 0; mt < 4; mt++)
                #pragma unroll
                for (int nt = 0; nt < 4; nt++)
                    asm volatile(
                        "mma.sync.aligned.m16n8k16.row.col.f32.f16.f16.f32 "
                        "{%0,%1,%2,%3}, {%4,%5,%6,%7}, {%8,%9}, {%0,%1,%2,%3};"
                        : "+f"(acc[mt][nt][0]), "+f"(acc[mt][nt][1]),
                          "+f"(acc[mt][nt][2]), "+f"(acc[mt][nt][3])
                        : "r"(af[mt][0]), "r"(af[mt][1]), "r"(af[mt][2]), "r"(af[mt][3]),
                          "r"(bf[nt][0]), "r"(bf[nt][1]));
        }
    };

    loadRegs(0);
    storeSmem(0);
    __syncthreads();

    const int nk = K / 32;
    for (int kt = 0; kt < nk; kt++) {
        if (kt + 1 < nk) loadRegs((kt + 1) * 32);
        compute(kt & 1);
        if (kt + 1 < nk) storeSmem((kt & 1) ^ 1);
        __syncthreads();
    }

    // ---- epilogue (m16n8 f32 accumulator fragment -> C)
    #pragma unroll
    for (int mt = 0; mt < 4; mt++) {
        const int r0 = m0 + wm + mt * 16 + grp;
        #pragma unroll
        for (int half = 0; half < 2; half++) {
            const int gm = r0 + half * 8;
            if (gm >= M) continue;
            #pragma unroll
            for (int nt = 0; nt < 4; nt++) {
                const int gn = n0 + wn + nt * 8 + idx * 2;
                float v0 = acc[mt][nt][half * 2 + 0];
                float v1 = acc[mt][nt][half * 2 + 1];
                if (HAS_BIAS) { v0 += bias[gn]; v1 += bias[gn + 1]; }
                if (DO_GELU)  { v0 = gelu_exact(v0); v1 = gelu_exact(v1); }
                float* p = C + (size_t)gm * N + gn;
                if (ACCUM) {
                    float2 old = *reinterpret_cast<float2*>(p);
                    v0 += old.x; v1 += old.y;
                }
                *reinterpret_cast<float2*>(p) = make_float2(v0, v1);
            }
        }
    }
}

// ---------------- weight transpose: in [R,C] -> out [C,R], per layer z ----------------
__global__ void transpose_kernel(const float* __restrict__ in, float* __restrict__ out,
                                 int R, int Cc)
{
    __shared__ float tile[32][33];
    const size_t lo = (size_t)blockIdx.z * R * Cc;
    const int c0 = blockIdx.x * 32, r0 = blockIdx.y * 32;
    const int x = threadIdx.x, y = threadIdx.y;
    #pragma unroll
    for (int j = 0; j < 32; j += 8)
        tile[y + j][x] = in[lo + (size_t)(r0 + y + j) * Cc + c0 + x];
    __syncthreads();
    #pragma unroll
    for (int j = 0; j < 32; j += 8)
        out[lo + (size_t)(c0 + y + j) * R + r0 + x] = tile[x][y + j];
}

// ---------------- im2col ----------------
__global__ void im2col_kernel(const float* __restrict__ x, float* __restrict__ out)
{
    const int total = B_ * NPATCH_ * W_;
    int idx = blockIdx.x * 256 + threadIdx.x;
    if (idx >= total) return;
    const int kk = idx % W_;
    const int r  = idx / W_;
    const int b  = r / NPATCH_;
    const int p  = r % NPATCH_;
    const int ph = p / 14, pw = p % 14;
    const int c  = kk >> 8;
    const int py = (kk >> 4) & 15;
    const int px = kk & 15;
    out[idx] = x[(((size_t)b * C_ + c) * IMG_ + ph * P_ + py) * IMG_ + pw * P_ + px];
}

// ---------------- assemble ----------------
__global__ void assemble_kernel(const float* __restrict__ tok,
                                const float* __restrict__ cls,
                                const float* __restrict__ pe,
                                float* __restrict__ h)
{
    int idx = blockIdx.x * 256 + threadIdx.x;
    if (idx >= BSW_) return;
    const int w  = idx % W_;
    const int bs = idx / W_;
    const int s  = bs % S_;
    const int b  = bs / S_;
    float v = (s == 0) ? cls[w] : tok[((size_t)b * NPATCH_ + (s - 1)) * W_ + w];
    h[idx] = v + pe[(size_t)s * W_ + w];
}

// ---------------- layernorm ----------------
__global__ void layernorm_kernel(const float* __restrict__ x,
                                 const float* __restrict__ gamma,
                                 const float* __restrict__ beta,
                                 float* __restrict__ y)
{
    const int row = blockIdx.x;
    const float* xr = x + (size_t)row * W_;
    float s = 0.f, s2 = 0.f;
    for (int i = threadIdx.x; i < W_; i += 256) {
        float v = xr[i];
        s += v; s2 += v * v;
    }
    for (int off = 16; off > 0; off >>= 1) {
        s  += __shfl_down_sync(0xffffffffu, s, off);
        s2 += __shfl_down_sync(0xffffffffu, s2, off);
    }
    __shared__ float rs[8], rs2[8];
    const int warp = threadIdx.x >> 5, lane = threadIdx.x & 31;
    if (lane == 0) { rs[warp] = s; rs2[warp] = s2; }
    __syncthreads();
    __shared__ float mean_sh, inv_sh;
    if (threadIdx.x == 0) {
        float ts = 0.f, ts2 = 0.f;
        for (int i = 0; i < 8; i++) { ts += rs[i]; ts2 += rs2[i]; }
        float mean = ts * (1.0f / W_);
        float var  = ts2 * (1.0f / W_) - mean * mean;
        mean_sh = mean;
        inv_sh  = rsqrtf(var + 1e-5f);
    }
    __syncthreads();
    const float mean = mean_sh, inv = inv_sh;
    float* yr = y + (size_t)row * W_;
    for (int i = threadIdx.x; i < W_; i += 256)
        yr[i] = (xr[i] - mean) * inv * gamma[i] + beta[i];
}

// ---------------- attention: scores ----------------
__global__ void attn_scores_kernel(const float* __restrict__ q,
                                   const float* __restrict__ k,
                                   float* __restrict__ att)
{
    const int z  = blockIdx.z;
    const int b  = z / H_, h = z % H_;
    const int s0 = blockIdx.y * 16;
    const int t0 = blockIdx.x * 16;

    __shared__ float qs[16][65];
    __shared__ float ks[16][65];

    const int t = threadIdx.x;
    const int r = t >> 4;
    const int c = (t & 15) * 4;

    const float* qbase = q + (size_t)b * S_ * W_ + h * HD_;
    const float* kbase = k + (size_t)b * S_ * W_ + h * HD_;

    const int gs = s0 + r;
    float4 qv = (gs < S_) ? *reinterpret_cast<const float4*>(qbase + (size_t)gs * W_ + c)
                          : make_float4(0.f, 0.f, 0.f, 0.f);
    qs[r][c] = qv.x; qs[r][c+1] = qv.y; qs[r][c+2] = qv.z; qs[r][c+3] = qv.w;

    const int gt = t0 + r;
    float4 kv = (gt < S_) ? *reinterpret_cast<const float4*>(kbase + (size_t)gt * W_ + c)
                          : make_float4(0.f, 0.f, 0.f, 0.f);
    ks[r][c] = kv.x; ks[r][c+1] = kv.y; ks[r][c+2] = kv.z; ks[r][c+3] = kv.w;
    __syncthreads();

    const int si = t >> 4, ti = t & 15;
    float acc = 0.f;
    #pragma unroll
    for (int d = 0; d < HD_; d++)
        acc = fmaf(qs[si][d], ks[ti][d], acc);

    const int gs2 = s0 + si, gt2 = t0 + ti;
    if (gs2 < S_ && gt2 < S_)
        att[((size_t)z * S_ + gs2) * S_ + gt2] = acc;
}

// ---------------- softmax ----------------
__global__ void softmax_kernel(float* __restrict__ att, int nrows)
{
    const int warp = blockIdx.x * 4 + (threadIdx.x >> 5);
    const int lane = threadIdx.x & 31;
    if (warp >= nrows) return;
    float* row = att + (size_t)warp * S_;

    float mx = -1e30f;
    for (int i = lane; i < S_; i += 32) mx = fmaxf(mx, row[i]);
    for (int off = 16; off > 0; off >>= 1)
        mx = fmaxf(mx, __shfl_xor_sync(0xffffffffu, mx, off));

    float sum = 0.f;
    for (int i = lane; i < S_; i += 32) {
        float e = expf((row[i] - mx) * 0.125f);
        row[i] = e;
        sum += e;
    }
    for (int off = 16; off > 0; off >>= 1)
        sum += __shfl_xor_sync(0xffffffffu, sum, off);
    const float inv = 1.0f / sum;
    for (int i = lane; i < S_; i += 32) row[i] *= inv;
}

// ---------------- o = att @ v ----------------
__global__ void attn_av_kernel(const float* __restrict__ att,
                               const float* __restrict__ v,
                               float* __restrict__ o)
{
    const int z  = blockIdx.y;
    const int b  = z / H_, h = z % H_;
    const int s0 = blockIdx.x * 16;

    __shared__ float as_[16][17];
    __shared__ float vs[16][65];

    const int si = threadIdx.x >> 4;
    const int dj = threadIdx.x & 15;

    float acc0 = 0.f, acc1 = 0.f, acc2 = 0.f, acc3 = 0.f;
    const float* vbase = v + (size_t)b * S_ * W_ + h * HD_;

    for (int t0 = 0; t0 < S_; t0 += 16) {
        float a = 0.f;
        if (s0 + si < S_ && t0 + dj < S_)
            a = att[((size_t)z * S_ + s0 + si) * S_ + t0 + dj];
        as_[si][dj] = a;

        const int r = si, c = dj * 4;
        float4 vv = (t0 + r < S_) ? *reinterpret_cast<const float4*>(vbase + (size_t)(t0 + r) * W_ + c)
                                  : make_float4(0.f, 0.f, 0.f, 0.f);
        vs[r][c] = vv.x; vs[r][c+1] = vv.y; vs[r][c+2] = vv.z; vs[r][c+3] = vv.w;
        __syncthreads();

        #pragma unroll
        for (int tt = 0; tt < 16; tt++) {
            const float a2 = as_[si][tt];
            acc0 = fmaf(a2, vs[tt][dj*4+0], acc0);
            acc1 = fmaf(a2, vs[tt][dj*4+1], acc1);
            acc2 = fmaf(a2, vs[tt][dj*4+2], acc2);
            acc3 = fmaf(a2, vs[tt][dj*4+3], acc3);
        }
        __syncthreads();
    }

    const int gs = s0 + si;
    if (gs < S_) {
        float* obase = o + (size_t)b * S_ * W_ + (size_t)gs * W_ + h * HD_ + dj * 4;
        obase[0] = acc0; obase[1] = acc1; obase[2] = acc2; obase[3] = acc3;
    }
}

// ---------------- gather / l2norm ----------------
__global__ void gather_cls_kernel(const float* __restrict__ h, float* __restrict__ cls)
{
    int idx = blockIdx.x * 256 + threadIdx.x;
    if (idx >= B_ * W_) return;
    const int b = idx / W_, w = idx % W_;
    cls[idx] = h[(size_t)b * S_ * W_ + w];
}

__global__ void l2norm_kernel(float* __restrict__ out)
{
    const int row = blockIdx.x;
    float* r = out + (size_t)row * E_;
    float s = 0.f;
    for (int i = threadIdx.x; i < E_; i += 256) { float v = r[i]; s += v * v; }
    for (int off = 16; off > 0; off >>= 1) s += __shfl_down_sync(0xffffffffu, s, off);
    __shared__ float rs[8];
    const int warp = threadIdx.x >> 5, lane = threadIdx.x & 31;
    if (lane == 0) rs[warp] = s;
    __syncthreads();
    __shared__ float inv_sh;
    if (threadIdx.x == 0) {
        float ts = 0.f;
        for (int i = 0; i < 8; i++) ts += rs[i];
        inv_sh = rsqrtf(ts);
    }
    __syncthreads();
    const float inv = inv_sh;
    for (int i = threadIdx.x; i < E_; i += 256) r[i] *= inv;
}

// ---------------- launch ----------------
extern "C" void kernel_launch(void* const* d_in, const int* in_sizes, int n_in,
                              void* d_out, int out_size)
{
    (void)in_sizes; (void)n_in; (void)out_size;

    const float* x       = (const float*)d_in[0];
    const float* conv_w  = (const float*)d_in[1];
    const float* conv_b  = (const float*)d_in[2];
    const float* cls_tok = (const float*)d_in[3];
    const float* pe      = (const float*)d_in[4];
    const float* ln1_g   = (const float*)d_in[5];
    const float* ln1_b   = (const float*)d_in[6];
    const float* wq      = (const float*)d_in[7];
    const float* bq      = (const float*)d_in[8];
    const float* wk      = (const float*)d_in[9];
    const float* bk      = (const float*)d_in[10];
    const float* wv      = (const float*)d_in[11];
    const float* bv      = (const float*)d_in[12];
    const float* wo      = (const float*)d_in[13];
    const float* bo      = (const float*)d_in[14];
    const float* ln2_g   = (const float*)d_in[15];
    const float* ln2_b   = (const float*)d_in[16];
    const float* w1      = (const float*)d_in[17];
    const float* b1      = (const float*)d_in[18];
    const float* w2      = (const float*)d_in[19];
    const float* b2      = (const float*)d_in[20];
    const float* proj    = (const float*)d_in[21];
    float* out           = (float*)d_out;

    float *h, *y, *q, *k, *v, *o, *att, *ff, *i2c, *tok, *cls;
    float *wqT, *wkT, *wvT, *woT, *w1T, *w2T, *projT;
    cudaGetSymbolAddress((void**)&h,   g_h);
    cudaGetSymbolAddress((void**)&y,   g_y);
    cudaGetSymbolAddress((void**)&q,   g_q);
    cudaGetSymbolAddress((void**)&k,   g_k);
    cudaGetSymbolAddress((void**)&v,   g_v);
    cudaGetSymbolAddress((void**)&o,   g_o);
    cudaGetSymbolAddress((void**)&att, g_att);
    cudaGetSymbolAddress((void**)&ff,  g_ff);
    cudaGetSymbolAddress((void**)&i2c, g_im2col);
    cudaGetSymbolAddress((void**)&tok, g_tok);
    cudaGetSymbolAddress((void**)&cls, g_cls);
    cudaGetSymbolAddress((void**)&wqT, g_wqT);
    cudaGetSymbolAddress((void**)&wkT, g_wkT);
    cudaGetSymbolAddress((void**)&wvT, g_wvT);
    cudaGetSymbolAddress((void**)&woT, g_woT);
    cudaGetSymbolAddress((void**)&w1T, g_w1T);
    cudaGetSymbolAddress((void**)&w2T, g_w2T);
    cudaGetSymbolAddress((void**)&projT, g_projT);

    const int M  = B_ * S_;       // 6304
    const int Mp = B_ * NPATCH_;  // 6272

    // --- weight transposes ([K,N] -> [N,K]) ---
    {
        dim3 blk(32, 8);
        transpose_kernel<<<dim3(W_/32,  W_/32,  L_), blk>>>(wq, wqT, W_, W_);
        transpose_kernel<<<dim3(W_/32,  W_/32,  L_), blk>>>(wk, wkT, W_, W_);
        transpose_kernel<<<dim3(W_/32,  W_/32,  L_), blk>>>(wv, wvT, W_, W_);
        transpose_kernel<<<dim3(W_/32,  W_/32,  L_), blk>>>(wo, woT, W_, W_);
        transpose_kernel<<<dim3(FF_/32, W_/32,  L_), blk>>>(w1, w1T, W_, FF_);
        transpose_kernel<<<dim3(W_/32,  FF_/32, L_), blk>>>(w2, w2T, FF_, W_);
        transpose_kernel<<<dim3(E_/32,  W_/32,  1),  blk>>>(proj, projT, W_, E_);
    }

    // --- patch embedding (conv_w is already [N=768, K=768]) ---
    {
        const int total = Mp * W_;
        im2col_kernel<<<(total + 255) / 256, 256>>>(x, i2c);
        dim3 grid(W_ / 128, (Mp + 127) / 128);
        gemm_hmma<1,0,0><<<grid, 256>>>(i2c, conv_w, conv_b, tok, Mp, W_, W_);
        assemble_kernel<<<(BSW_ + 255) / 256, 256>>>(tok, cls_tok, pe, h);
    }

    const int nrows_att = B_ * H_ * S_;
    dim3 gridW (W_  / 128, (M + 127) / 128);
    dim3 gridFF(FF_ / 128, (M + 127) / 128);
    dim3 gridSc(13, 13, B_ * H_);
    dim3 gridAv(13, B_ * H_);

    for (int l = 0; l < L_; l++) {
        const size_t wOff = (size_t)l * W_ * W_;
        const size_t bOff = (size_t)l * W_;

        layernorm_kernel<<<M, 256>>>(h, ln1_g + bOff, ln1_b + bOff, y);
        gemm_hmma<1,0,0><<<gridW, 256>>>(y, wqT + wOff, bq + bOff, q, M, W_, W_);
        gemm_hmma<1,0,0><<<gridW, 256>>>(y, wkT + wOff, bk + bOff, k, M, W_, W_);
        gemm_hmma<1,0,0><<<gridW, 256>>>(y, wvT + wOff, bv + bOff, v, M, W_, W_);
        attn_scores_kernel<<<gridSc, 256>>>(q, k, att);
        softmax_kernel<<<(nrows_att + 3) / 4, 128>>>(att, nrows_att);
        attn_av_kernel<<<gridAv, 256>>>(att, v, o);
        gemm_hmma<1,1,0><<<gridW, 256>>>(o, woT + wOff, bo + bOff, h, M, W_, W_);
        layernorm_kernel<<<M, 256>>>(h, ln2_g + bOff, ln2_b + bOff, y);
        gemm_hmma<1,0,1><<<gridFF, 256>>>(y, w1T + (size_t)l * W_ * FF_,
                                          b1 + (size_t)l * FF_, ff, M, FF_, W_);
        gemm_hmma<1,1,0><<<gridW, 256>>>(ff, w2T + (size_t)l * FF_ * W_,
                                         b2 + bOff, h, M, W_, FF_);
    }

    gather_cls_kernel<<<(B_ * W_ + 255) / 256, 256>>>(h, cls);
    {
        dim3 grid(E_ / 128, 1);
        gemm_hmma<0,0,0><<<grid, 256>>>(cls, projT, nullptr, out, B_, E_, W_);
    }
    l2norm_kernel<<<B_, 256>>>(out);
}

// round 6
// speedup vs baseline: 1.3904x; 1.3904x over previous
#include <cuda_runtime.h>
#include <cuda_fp16.h>
#include <math.h>
#include <stdint.h>

// ---------------- problem constants ----------------
#define B_  32
#define C_  3
#define IMG_ 224
#define P_  16
#define W_  768
#define L_  12
#define H_  12
#define S_  197
#define HD_ 64
#define FF_ 3072
#define E_  512
#define NPATCH_ 196
#define BSW_ (B_*S_*W_)

// ---------------- scratch (no cudaMalloc allowed) ----------------
__device__ float  g_h   [BSW_];
__device__ __half g_y   [BSW_];              // LN output (GEMM A operand)
__device__ float  g_q   [BSW_];
__device__ float  g_k   [BSW_];
__device__ float  g_v   [BSW_];
__device__ __half g_o   [BSW_];              // attn output (GEMM A operand)
__device__ float  g_att [B_*H_*S_*S_];
__device__ __half g_ff  [B_*S_*FF_];         // FF1 output (GEMM A operand)
__device__ __half g_im2col[B_*NPATCH_*W_];
__device__ float  g_tok [B_*NPATCH_*W_];
__device__ __half g_cls [B_*W_];
// fp16 weights, [N,K] K-contiguous (B operand)
__device__ __half g_convw16[W_*W_];
__device__ __half g_wqT [L_*W_*W_];
__device__ __half g_wkT [L_*W_*W_];
__device__ __half g_wvT [L_*W_*W_];
__device__ __half g_woT [L_*W_*W_];
__device__ __half g_w1T [L_*W_*FF_];
__device__ __half g_w2T [L_*FF_*W_];
__device__ __half g_projT[W_*E_];

__device__ __forceinline__ float gelu_exact(float v) {
    return 0.5f * v * (1.0f + erff(v * 0.70710678118654752f));
}
__device__ __forceinline__ uint32_t smem_u32(const void* p) {
    uint32_t a;
    asm("{ .reg .u64 t; cvta.to.shared.u64 t, %1; cvt.u32.u64 %0, t; }" : "=r"(a) : "l"(p));
    return a;
}

#define LDSM_X4(r, addr) \
    asm volatile("ldmatrix.sync.aligned.m8n8.x4.shared.b16 {%0,%1,%2,%3}, [%4];" \
        : "=r"((r)[0]), "=r"((r)[1]), "=r"((r)[2]), "=r"((r)[3]) : "r"(addr))
#define LDSM_X2(r, addr) \
    asm volatile("ldmatrix.sync.aligned.m8n8.x2.shared.b16 {%0,%1}, [%2];" \
        : "=r"((r)[0]), "=r"((r)[1]) : "r"(addr))

__device__ __forceinline__ void cp16(uint32_t dst, const void* src, bool valid) {
    int sz = valid ? 16 : 0;
    asm volatile("cp.async.cg.shared.global [%0], [%1], 16, %2;"
                 :: "r"(dst), "l"(src), "r"(sz));
}
#define CP_COMMIT() asm volatile("cp.async.commit_group;" ::: "memory")
#define CP_WAIT2()  asm volatile("cp.async.wait_group 2;" ::: "memory")

// ============ fp16 HMMA GEMM, 4-stage cp.async pipeline ============
// C[M,N] = A[M,K] @ Bt[N,K]^T (+bias/gelu/residual). A,Bt fp16; out fp32 or fp16.
// Block 128x128, K-tile 32. 8 warps x (64x32). smem rows: 64B data + 16B pad.
#define STRIDE 80
#define STAGEB (128 * STRIDE)         // 10240 B
#define STAGES 4
#define GEMM_SMEM (2 * STAGES * STAGEB)   // 81920 B

template<int HAS_BIAS, int ACCUM, int DO_GELU, int OUT_HALF>
__global__ __launch_bounds__(256)
void gemm_f16(const __half* __restrict__ A, const __half* __restrict__ Bt,
              const float* __restrict__ bias, float* __restrict__ C,
              __half* __restrict__ Ch, int M, int N, int K)
{
    extern __shared__ __align__(128) uint8_t sm[];
    uint8_t* smA = sm;
    uint8_t* smB = sm + STAGES * STAGEB;

    const int t    = threadIdx.x;
    const int warp = t >> 5, lane = t & 31;
    const int m0   = blockIdx.y * 128;
    const int n0   = blockIdx.x * 128;
    const int wm   = (warp >> 2) * 64;
    const int wn   = (warp & 3) * 32;
    const int grp  = lane >> 2;
    const int idx  = lane & 3;

    float acc[4][4][4];
    #pragma unroll
    for (int a = 0; a < 4; a++)
        #pragma unroll
        for (int b = 0; b < 4; b++)
            #pragma unroll
            for (int c = 0; c < 4; c++) acc[a][b][c] = 0.0f;

    const uint32_t saA = smem_u32(smA);
    const uint32_t saB = smem_u32(smB);

    // cp.async mapping: thread -> (row, two 16B chunks)
    const int rowL = t >> 1;          // 0..127
    const int ck0  = (t & 1) * 2;     // 16B-chunk index 0 or 2

    const bool aValid = (m0 + rowL) < M;
    const __half* aBase = A + (size_t)(m0 + rowL) * K + ck0 * 8;
    const __half* bBase = Bt + (size_t)(n0 + rowL) * K + ck0 * 8;
    const uint32_t dA = saA + rowL * STRIDE + ck0 * 16;
    const uint32_t dB = saB + rowL * STRIDE + ck0 * 16;

    auto load_stage = [&](int kt, int buf) {
        const __half* pa = aBase + kt * 32;
        const __half* pb = bBase + kt * 32;
        cp16(dA + buf * STAGEB,      pa,     aValid);
        cp16(dA + buf * STAGEB + 16, pa + 8, aValid);
        cp16(dB + buf * STAGEB,      pb,     true);
        cp16(dB + buf * STAGEB + 16, pb + 8, true);
    };

    // fragment fetch offsets
    const int aoff = (wm + (lane & 15)) * STRIDE + (lane >> 4) * 16;
    const int boff = (wn + (lane & 7))  * STRIDE + ((lane >> 3) & 1) * 16;

    auto compute = [&](int buf) {
        const uint32_t sa = saA + buf * STAGEB;
        const uint32_t sb = saB + buf * STAGEB;
        #pragma unroll
        for (int ks = 0; ks < 2; ks++) {
            uint32_t af[4][4], bf[4][2];
            #pragma unroll
            for (int mt = 0; mt < 4; mt++)
                LDSM_X4(af[mt], sa + aoff + mt * 16 * STRIDE + ks * 32);
            #pragma unroll
            for (int nt = 0; nt < 4; nt++)
                LDSM_X2(bf[nt], sb + boff + nt * 8 * STRIDE + ks * 32);
            #pragma unroll
            for (int mt = 0; mt < 4; mt++)
                #pragma unroll
                for (int nt = 0; nt < 4; nt++)
                    asm volatile(
                        "mma.sync.aligned.m16n8k16.row.col.f32.f16.f16.f32 "
                        "{%0,%1,%2,%3}, {%4,%5,%6,%7}, {%8,%9}, {%0,%1,%2,%3};"
                        : "+f"(acc[mt][nt][0]), "+f"(acc[mt][nt][1]),
                          "+f"(acc[mt][nt][2]), "+f"(acc[mt][nt][3])
                        : "r"(af[mt][0]), "r"(af[mt][1]), "r"(af[mt][2]), "r"(af[mt][3]),
                          "r"(bf[nt][0]), "r"(bf[nt][1]));
        }
    };

    const int nk = K / 32;   // >= 16 at every call site

    // prefetch 3 stages
    #pragma unroll
    for (int s = 0; s < STAGES - 1; s++) {
        load_stage(s, s);
        CP_COMMIT();
    }

    for (int kt = 0; kt < nk; kt++) {
        CP_WAIT2();
        __syncthreads();
        // always commit exactly one group per iteration (possibly empty)
        if (kt + STAGES - 1 < nk) load_stage(kt + STAGES - 1, (kt + STAGES - 1) & 3);
        CP_COMMIT();
        compute(kt & 3);
    }

    // ---- epilogue (m16n8 f32 accumulator fragment -> C)
    #pragma unroll
    for (int mt = 0; mt < 4; mt++) {
        const int r0 = m0 + wm + mt * 16 + grp;
        #pragma unroll
        for (int half = 0; half < 2; half++) {
            const int gm = r0 + half * 8;
            if (gm >= M) continue;
            #pragma unroll
            for (int nt = 0; nt < 4; nt++) {
                const int gn = n0 + wn + nt * 8 + idx * 2;
                float v0 = acc[mt][nt][half * 2 + 0];
                float v1 = acc[mt][nt][half * 2 + 1];
                if (HAS_BIAS) { v0 += bias[gn]; v1 += bias[gn + 1]; }
                if (DO_GELU)  { v0 = gelu_exact(v0); v1 = gelu_exact(v1); }
                if (OUT_HALF) {
                    *reinterpret_cast<__half2*>(Ch + (size_t)gm * N + gn) =
                        __floats2half2_rn(v0, v1);
                } else {
                    float* p = C + (size_t)gm * N + gn;
                    if (ACCUM) {
                        float2 old = *reinterpret_cast<float2*>(p);
                        v0 += old.x; v1 += old.y;
                    }
                    *reinterpret_cast<float2*>(p) = make_float2(v0, v1);
                }
            }
        }
    }
}

// ---------------- weight transpose to fp16: in [R,C] f32 -> out [C,R] f16 ----------------
__global__ void transpose_h_kernel(const float* __restrict__ in, __half* __restrict__ out,
                                   int R, int Cc)
{
    __shared__ float tile[32][33];
    const size_t li = (size_t)blockIdx.z * R * Cc;
    const int c0 = blockIdx.x * 32, r0 = blockIdx.y * 32;
    const int x = threadIdx.x, y = threadIdx.y;
    #pragma unroll
    for (int j = 0; j < 32; j += 8)
        tile[y + j][x] = in[li + (size_t)(r0 + y + j) * Cc + c0 + x];
    __syncthreads();
    #pragma unroll
    for (int j = 0; j < 32; j += 8)
        out[li + (size_t)(c0 + y + j) * R + r0 + x] = __float2half(tile[x][y + j]);
}

// ---------------- conv_w fp32 -> fp16 (already [N,K]) ----------------
__global__ void convw_h_kernel(const float* __restrict__ in, __half* __restrict__ out)
{
    int i = blockIdx.x * 256 + threadIdx.x;
    if (i < W_ * W_) out[i] = __float2half(in[i]);
}

// ---------------- im2col (fp16 out) ----------------
__global__ void im2col_kernel(const float* __restrict__ x, __half* __restrict__ out)
{
    const int total = B_ * NPATCH_ * W_;
    int idx = blockIdx.x * 256 + threadIdx.x;
    if (idx >= total) return;
    const int kk = idx % W_;
    const int r  = idx / W_;
    const int b  = r / NPATCH_;
    const int p  = r % NPATCH_;
    const int ph = p / 14, pw = p % 14;
    const int c  = kk >> 8;
    const int py = (kk >> 4) & 15;
    const int px = kk & 15;
    out[idx] = __float2half(
        x[(((size_t)b * C_ + c) * IMG_ + ph * P_ + py) * IMG_ + pw * P_ + px]);
}

// ---------------- assemble h = [cls; tokens] + pe (fp32) ----------------
__global__ void assemble_kernel(const float* __restrict__ tok,
                                const float* __restrict__ cls,
                                const float* __restrict__ pe,
                                float* __restrict__ h)
{
    int idx = blockIdx.x * 256 + threadIdx.x;
    if (idx >= BSW_) return;
    const int w  = idx % W_;
    const int bs = idx / W_;
    const int s  = bs % S_;
    const int b  = bs / S_;
    float v = (s == 0) ? cls[w] : tok[((size_t)b * NPATCH_ + (s - 1)) * W_ + w];
    h[idx] = v + pe[(size_t)s * W_ + w];
}

// ---------------- layernorm (fp32 in, fp16 out) ----------------
__global__ void layernorm_kernel(const float* __restrict__ x,
                                 const float* __restrict__ gamma,
                                 const float* __restrict__ beta,
                                 __half* __restrict__ y)
{
    const int row = blockIdx.x;
    const float* xr = x + (size_t)row * W_;
    float s = 0.f, s2 = 0.f;
    for (int i = threadIdx.x; i < W_; i += 256) {
        float v = xr[i];
        s += v; s2 += v * v;
    }
    for (int off = 16; off > 0; off >>= 1) {
        s  += __shfl_down_sync(0xffffffffu, s, off);
        s2 += __shfl_down_sync(0xffffffffu, s2, off);
    }
    __shared__ float rs[8], rs2[8];
    const int warp = threadIdx.x >> 5, lane = threadIdx.x & 31;
    if (lane == 0) { rs[warp] = s; rs2[warp] = s2; }
    __syncthreads();
    __shared__ float mean_sh, inv_sh;
    if (threadIdx.x == 0) {
        float ts = 0.f, ts2 = 0.f;
        for (int i = 0; i < 8; i++) { ts += rs[i]; ts2 += rs2[i]; }
        float mean = ts * (1.0f / W_);
        float var  = ts2 * (1.0f / W_) - mean * mean;
        mean_sh = mean;
        inv_sh  = rsqrtf(var + 1e-5f);
    }
    __syncthreads();
    const float mean = mean_sh, inv = inv_sh;
    __half* yr = y + (size_t)row * W_;
    for (int i = threadIdx.x; i < W_; i += 256)
        yr[i] = __float2half((xr[i] - mean) * inv * gamma[i] + beta[i]);
}

// ---------------- attention: scores ----------------
__global__ void attn_scores_kernel(const float* __restrict__ q,
                                   const float* __restrict__ k,
                                   float* __restrict__ att)
{
    const int z  = blockIdx.z;
    const int b  = z / H_, h = z % H_;
    const int s0 = blockIdx.y * 16;
    const int t0 = blockIdx.x * 16;

    __shared__ float qs[16][65];
    __shared__ float ks[16][65];

    const int t = threadIdx.x;
    const int r = t >> 4;
    const int c = (t & 15) * 4;

    const float* qbase = q + (size_t)b * S_ * W_ + h * HD_;
    const float* kbase = k + (size_t)b * S_ * W_ + h * HD_;

    const int gs = s0 + r;
    float4 qv = (gs < S_) ? *reinterpret_cast<const float4*>(qbase + (size_t)gs * W_ + c)
                          : make_float4(0.f, 0.f, 0.f, 0.f);
    qs[r][c] = qv.x; qs[r][c+1] = qv.y; qs[r][c+2] = qv.z; qs[r][c+3] = qv.w;

    const int gt = t0 + r;
    float4 kv = (gt < S_) ? *reinterpret_cast<const float4*>(kbase + (size_t)gt * W_ + c)
                          : make_float4(0.f, 0.f, 0.f, 0.f);
    ks[r][c] = kv.x; ks[r][c+1] = kv.y; ks[r][c+2] = kv.z; ks[r][c+3] = kv.w;
    __syncthreads();

    const int si = t >> 4, ti = t & 15;
    float acc = 0.f;
    #pragma unroll
    for (int d = 0; d < HD_; d++)
        acc = fmaf(qs[si][d], ks[ti][d], acc);

    const int gs2 = s0 + si, gt2 = t0 + ti;
    if (gs2 < S_ && gt2 < S_)
        att[((size_t)z * S_ + gs2) * S_ + gt2] = acc;
}

// ---------------- softmax ----------------
__global__ void softmax_kernel(float* __restrict__ att, int nrows)
{
    const int warp = blockIdx.x * 4 + (threadIdx.x >> 5);
    const int lane = threadIdx.x & 31;
    if (warp >= nrows) return;
    float* row = att + (size_t)warp * S_;

    float mx = -1e30f;
    for (int i = lane; i < S_; i += 32) mx = fmaxf(mx, row[i]);
    for (int off = 16; off > 0; off >>= 1)
        mx = fmaxf(mx, __shfl_xor_sync(0xffffffffu, mx, off));

    float sum = 0.f;
    for (int i = lane; i < S_; i += 32) {
        float e = expf((row[i] - mx) * 0.125f);
        row[i] = e;
        sum += e;
    }
    for (int off = 16; off > 0; off >>= 1)
        sum += __shfl_xor_sync(0xffffffffu, sum, off);
    const float inv = 1.0f / sum;
    for (int i = lane; i < S_; i += 32) row[i] *= inv;
}

// ---------------- o = att @ v (fp16 out) ----------------
__global__ void attn_av_kernel(const float* __restrict__ att,
                               const float* __restrict__ v,
                               __half* __restrict__ o)
{
    const int z  = blockIdx.y;
    const int b  = z / H_, h = z % H_;
    const int s0 = blockIdx.x * 16;

    __shared__ float as_[16][17];
    __shared__ float vs[16][65];

    const int si = threadIdx.x >> 4;
    const int dj = threadIdx.x & 15;

    float acc0 = 0.f, acc1 = 0.f, acc2 = 0.f, acc3 = 0.f;
    const float* vbase = v + (size_t)b * S_ * W_ + h * HD_;

    for (int t0 = 0; t0 < S_; t0 += 16) {
        float a = 0.f;
        if (s0 + si < S_ && t0 + dj < S_)
            a = att[((size_t)z * S_ + s0 + si) * S_ + t0 + dj];
        as_[si][dj] = a;

        const int r = si, c = dj * 4;
        float4 vv = (t0 + r < S_) ? *reinterpret_cast<const float4*>(vbase + (size_t)(t0 + r) * W_ + c)
                                  : make_float4(0.f, 0.f, 0.f, 0.f);
        vs[r][c] = vv.x; vs[r][c+1] = vv.y; vs[r][c+2] = vv.z; vs[r][c+3] = vv.w;
        __syncthreads();

        #pragma unroll
        for (int tt = 0; tt < 16; tt++) {
            const float a2 = as_[si][tt];
            acc0 = fmaf(a2, vs[tt][dj*4+0], acc0);
            acc1 = fmaf(a2, vs[tt][dj*4+1], acc1);
            acc2 = fmaf(a2, vs[tt][dj*4+2], acc2);
            acc3 = fmaf(a2, vs[tt][dj*4+3], acc3);
        }
        __syncthreads();
    }

    const int gs = s0 + si;
    if (gs < S_) {
        __half* obase = o + (size_t)b * S_ * W_ + (size_t)gs * W_ + h * HD_ + dj * 4;
        obase[0] = __float2half(acc0);
        obase[1] = __float2half(acc1);
        obase[2] = __float2half(acc2);
        obase[3] = __float2half(acc3);
    }
}

// ---------------- gather / l2norm ----------------
__global__ void gather_cls_kernel(const float* __restrict__ h, __half* __restrict__ cls)
{
    int idx = blockIdx.x * 256 + threadIdx.x;
    if (idx >= B_ * W_) return;
    const int b = idx / W_, w = idx % W_;
    cls[idx] = __float2half(h[(size_t)b * S_ * W_ + w]);
}

__global__ void l2norm_kernel(float* __restrict__ out)
{
    const int row = blockIdx.x;
    float* r = out + (size_t)row * E_;
    float s = 0.f;
    for (int i = threadIdx.x; i < E_; i += 256) { float v = r[i]; s += v * v; }
    for (int off = 16; off > 0; off >>= 1) s += __shfl_down_sync(0xffffffffu, s, off);
    __shared__ float rs[8];
    const int warp = threadIdx.x >> 5, lane = threadIdx.x & 31;
    if (lane == 0) rs[warp] = s;
    __syncthreads();
    __shared__ float inv_sh;
    if (threadIdx.x == 0) {
        float ts = 0.f;
        for (int i = 0; i < 8; i++) ts += rs[i];
        inv_sh = rsqrtf(ts);
    }
    __syncthreads();
    const float inv = inv_sh;
    for (int i = threadIdx.x; i < E_; i += 256) r[i] *= inv;
}

// ---------------- launch ----------------
extern "C" void kernel_launch(void* const* d_in, const int* in_sizes, int n_in,
                              void* d_out, int out_size)
{
    (void)in_sizes; (void)n_in; (void)out_size;

    const float* x       = (const float*)d_in[0];
    const float* conv_w  = (const float*)d_in[1];
    const float* conv_b  = (const float*)d_in[2];
    const float* cls_tok = (const float*)d_in[3];
    const float* pe      = (const float*)d_in[4];
    const float* ln1_g   = (const float*)d_in[5];
    const float* ln1_b   = (const float*)d_in[6];
    const float* wq      = (const float*)d_in[7];
    const float* bq      = (const float*)d_in[8];
    const float* wk      = (const float*)d_in[9];
    const float* bk      = (const float*)d_in[10];
    const float* wv      = (const float*)d_in[11];
    const float* bv      = (const float*)d_in[12];
    const float* wo      = (const float*)d_in[13];
    const float* bo      = (const float*)d_in[14];
    const float* ln2_g   = (const float*)d_in[15];
    const float* ln2_b   = (const float*)d_in[16];
    const float* w1      = (const float*)d_in[17];
    const float* b1      = (const float*)d_in[18];
    const float* w2      = (const float*)d_in[19];
    const float* b2      = (const float*)d_in[20];
    const float* proj    = (const float*)d_in[21];
    float* out           = (float*)d_out;

    float  *h, *q, *k, *v, *att, *tok;
    __half *y, *o, *ff, *i2c, *cls, *convw16;
    __half *wqT, *wkT, *wvT, *woT, *w1T, *w2T, *projT;
    cudaGetSymbolAddress((void**)&h,   g_h);
    cudaGetSymbolAddress((void**)&y,   g_y);
    cudaGetSymbolAddress((void**)&q,   g_q);
    cudaGetSymbolAddress((void**)&k,   g_k);
    cudaGetSymbolAddress((void**)&v,   g_v);
    cudaGetSymbolAddress((void**)&o,   g_o);
    cudaGetSymbolAddress((void**)&att, g_att);
    cudaGetSymbolAddress((void**)&ff,  g_ff);
    cudaGetSymbolAddress((void**)&i2c, g_im2col);
    cudaGetSymbolAddress((void**)&tok, g_tok);
    cudaGetSymbolAddress((void**)&cls, g_cls);
    cudaGetSymbolAddress((void**)&convw16, g_convw16);
    cudaGetSymbolAddress((void**)&wqT, g_wqT);
    cudaGetSymbolAddress((void**)&wkT, g_wkT);
    cudaGetSymbolAddress((void**)&wvT, g_wvT);
    cudaGetSymbolAddress((void**)&woT, g_woT);
    cudaGetSymbolAddress((void**)&w1T, g_w1T);
    cudaGetSymbolAddress((void**)&w2T, g_w2T);
    cudaGetSymbolAddress((void**)&projT, g_projT);

    cudaFuncSetAttribute(gemm_f16<1,0,0,0>, cudaFuncAttributeMaxDynamicSharedMemorySize, GEMM_SMEM);
    cudaFuncSetAttribute(gemm_f16<1,1,0,0>, cudaFuncAttributeMaxDynamicSharedMemorySize, GEMM_SMEM);
    cudaFuncSetAttribute(gemm_f16<1,0,1,1>, cudaFuncAttributeMaxDynamicSharedMemorySize, GEMM_SMEM);
    cudaFuncSetAttribute(gemm_f16<0,0,0,0>, cudaFuncAttributeMaxDynamicSharedMemorySize, GEMM_SMEM);

    const int M  = B_ * S_;       // 6304
    const int Mp = B_ * NPATCH_;  // 6272
    dim3 blkT(32, 8);

    // Launch order chosen so launch #6 (ncu -s 5 -c 1) is a GEMM.
    im2col_kernel<<<(Mp * W_ + 255) / 256, 256>>>(x, i2c);                       // 1
    convw_h_kernel<<<(W_ * W_ + 255) / 256, 256>>>(conv_w, convw16);             // 2
    transpose_h_kernel<<<dim3(FF_/32, W_/32,  L_), blkT>>>(w1, w1T, W_, FF_);    // 3
    transpose_h_kernel<<<dim3(W_/32,  FF_/32, L_), blkT>>>(w2, w2T, FF_, W_);    // 4
    transpose_h_kernel<<<dim3(W_/32,  W_/32,  L_), blkT>>>(wq, wqT, W_, W_);     // 5
    {
        dim3 grid(W_ / 128, (Mp + 127) / 128);
        gemm_f16<1,0,0,0><<<grid, 256, GEMM_SMEM>>>(i2c, convw16, conv_b,
                                                    tok, nullptr, Mp, W_, W_);   // 6 <- profiled
    }
    transpose_h_kernel<<<dim3(W_/32, W_/32, L_), blkT>>>(wk, wkT, W_, W_);
    transpose_h_kernel<<<dim3(W_/32, W_/32, L_), blkT>>>(wv, wvT, W_, W_);
    transpose_h_kernel<<<dim3(W_/32, W_/32, L_), blkT>>>(wo, woT, W_, W_);
    transpose_h_kernel<<<dim3(E_/32, W_/32, 1),  blkT>>>(proj, projT, W_, E_);
    assemble_kernel<<<(BSW_ + 255) / 256, 256>>>(tok, cls_tok, pe, h);

    const int nrows_att = B_ * H_ * S_;
    dim3 gridW (W_  / 128, (M + 127) / 128);
    dim3 gridFF(FF_ / 128, (M + 127) / 128);
    dim3 gridSc(13, 13, B_ * H_);
    dim3 gridAv(13, B_ * H_);

    for (int l = 0; l < L_; l++) {
        const size_t wOff = (size_t)l * W_ * W_;
        const size_t bOff = (size_t)l * W_;

        layernorm_kernel<<<M, 256>>>(h, ln1_g + bOff, ln1_b + bOff, y);
        gemm_f16<1,0,0,0><<<gridW, 256, GEMM_SMEM>>>(y, wqT + wOff, bq + bOff, q, nullptr, M, W_, W_);
        gemm_f16<1,0,0,0><<<gridW, 256, GEMM_SMEM>>>(y, wkT + wOff, bk + bOff, k, nullptr, M, W_, W_);
        gemm_f16<1,0,0,0><<<gridW, 256, GEMM_SMEM>>>(y, wvT + wOff, bv + bOff, v, nullptr, M, W_, W_);
        attn_scores_kernel<<<gridSc, 256>>>(q, k, att);
        softmax_kernel<<<(nrows_att + 3) / 4, 128>>>(att, nrows_att);
        attn_av_kernel<<<gridAv, 256>>>(att, v, o);
        gemm_f16<1,1,0,0><<<gridW, 256, GEMM_SMEM>>>(o, woT + wOff, bo + bOff, h, nullptr, M, W_, W_);
        layernorm_kernel<<<M, 256>>>(h, ln2_g + bOff, ln2_b + bOff, y);
        gemm_f16<1,0,1,1><<<gridFF, 256, GEMM_SMEM>>>(y, w1T + (size_t)l * W_ * FF_,
                                                      b1 + (size_t)l * FF_, nullptr, ff, M, FF_, W_);
        gemm_f16<1,1,0,0><<<gridW, 256, GEMM_SMEM>>>(ff, w2T + (size_t)l * FF_ * W_,
                                                     b2 + bOff, h, nullptr, M, W_, FF_);
    }

    gather_cls_kernel<<<(B_ * W_ + 255) / 256, 256>>>(h, cls);
    {
        dim3 grid(E_ / 128, 1);
        gemm_f16<0,0,0,0><<<grid, 256, GEMM_SMEM>>>(cls, projT, nullptr, out, nullptr, B_, E_, W_);
    }
    l2norm_kernel<<<B_, 256>>>(out);
}

// round 7
// speedup vs baseline: 2.4687x; 1.7755x over previous
#include <cuda_runtime.h>
#include <cuda_fp16.h>
#include <math.h>
#include <stdint.h>

// ---------------- problem constants ----------------
#define B_  32
#define C_  3
#define IMG_ 224
#define P_  16
#define W_  768
#define L_  12
#define H_  12
#define S_  197
#define HD_ 64
#define FF_ 3072
#define E_  512
#define NPATCH_ 196
#define BSW_ (B_*S_*W_)
#define SP_ 224            // padded S for K-dim of AV (multiple of 32)
#define ALD_ 256           // att fp32 row stride

// ---------------- scratch ----------------
__device__ float  g_h   [BSW_];
__device__ __half g_y   [BSW_];
__device__ __half g_qh  [BSW_];
__device__ __half g_kh  [BSW_];
__device__ __half g_vT  [B_*H_*HD_*SP_];     // [b,h,d,t] fp16, t-padded
__device__ __half g_o   [BSW_];
__device__ float  g_att [B_*H_*S_*ALD_];     // scores fp32, ld 256
__device__ __half g_atth[B_*H_*S_*SP_];      // softmax out fp16, ld 224
__device__ __half g_ff  [B_*S_*FF_];
__device__ __half g_im2col[B_*NPATCH_*W_];
__device__ float  g_tok [B_*NPATCH_*W_];
__device__ __half g_cls [B_*W_];
__device__ __half g_convw16[W_*W_];
__device__ __half g_wqT [L_*W_*W_];
__device__ __half g_wkT [L_*W_*W_];
__device__ __half g_wvT [L_*W_*W_];
__device__ __half g_woT [L_*W_*W_];
__device__ __half g_w1T [L_*W_*FF_];
__device__ __half g_w2T [L_*FF_*W_];
__device__ __half g_projT[W_*E_];

__device__ __forceinline__ float gelu_exact(float v) {
    return 0.5f * v * (1.0f + erff(v * 0.70710678118654752f));
}
__device__ __forceinline__ uint32_t smem_u32(const void* p) {
    uint32_t a;
    asm("{ .reg .u64 t; cvta.to.shared.u64 t, %1; cvt.u32.u64 %0, t; }" : "=r"(a) : "l"(p));
    return a;
}

#define LDSM_X4(r, addr) \
    asm volatile("ldmatrix.sync.aligned.m8n8.x4.shared.b16 {%0,%1,%2,%3}, [%4];" \
        : "=r"((r)[0]), "=r"((r)[1]), "=r"((r)[2]), "=r"((r)[3]) : "r"(addr))
#define LDSM_X2(r, addr) \
    asm volatile("ldmatrix.sync.aligned.m8n8.x2.shared.b16 {%0,%1}, [%2];" \
        : "=r"((r)[0]), "=r"((r)[1]) : "r"(addr))

__device__ __forceinline__ void cp16(uint32_t dst, const void* src, bool valid) {
    int sz = valid ? 16 : 0;
    asm volatile("cp.async.cg.shared.global [%0], [%1], 16, %2;"
                 :: "r"(dst), "l"(src), "r"(sz));
}
#define CP_COMMIT() asm volatile("cp.async.commit_group;" ::: "memory")
#define CP_WAIT2()  asm volatile("cp.async.wait_group 2;" ::: "memory")

// ============ generalized fp16 HMMA GEMM, 4-stage cp.async ============
// C[M,N] = A[M,K] @ Bt[N,K]^T. Batched over grid.z: z -> (b = z/H_, hh = z%H_),
// operand offsets += b*Bs + hh*Hs. OUT_MODE: 0 = f32 C (opt ACCUM), 1 = f16 Ch,
// 2 = per-head transposed V (vT[b,h,d,s], ld SP_).
#define STRIDE 80
#define STAGEB (128 * STRIDE)
#define STAGES 4
#define GEMM_SMEM (2 * STAGES * STAGEB)   // 81920 B

template<int HAS_BIAS, int ACCUM, int DO_GELU, int OUT_MODE>
__global__ __launch_bounds__(256)
void gemm_f16(const __half* __restrict__ A, const __half* __restrict__ Bt,
              const float* __restrict__ bias, float* __restrict__ C,
              __half* __restrict__ Ch, int M, int N, int K,
              int lda, int ldb, int ldc,
              long long aBs, long long aHs, long long bBs, long long bHs,
              long long cBs, long long cHs)
{
    extern __shared__ __align__(128) uint8_t sm[];
    uint8_t* smA = sm;
    uint8_t* smB = sm + STAGES * STAGEB;

    const int z = blockIdx.z;
    const int zb = z / H_, zh = z % H_;
    A  += (size_t)zb * aBs + (size_t)zh * aHs;
    Bt += (size_t)zb * bBs + (size_t)zh * bHs;
    const long long cOff = (long long)zb * cBs + (long long)zh * cHs;

    const int t    = threadIdx.x;
    const int warp = t >> 5, lane = t & 31;
    const int m0   = blockIdx.y * 128;
    const int n0   = blockIdx.x * 128;
    const int wm   = (warp >> 2) * 64;
    const int wn   = (warp & 3) * 32;
    const int grp  = lane >> 2;
    const int idx  = lane & 3;

    float acc[4][4][4];
    #pragma unroll
    for (int a = 0; a < 4; a++)
        #pragma unroll
        for (int b = 0; b < 4; b++)
            #pragma unroll
            for (int c = 0; c < 4; c++) acc[a][b][c] = 0.0f;

    const uint32_t saA = smem_u32(smA);
    const uint32_t saB = smem_u32(smB);

    const int rowL = t >> 1;
    const int ck0  = (t & 1) * 2;

    const bool aValid = (m0 + rowL) < M;
    const bool bValid = (n0 + rowL) < N;
    const __half* aBase = A + (size_t)(m0 + rowL) * lda + ck0 * 8;
    const __half* bBase = Bt + (size_t)(n0 + rowL) * ldb + ck0 * 8;
    const uint32_t dA = saA + rowL * STRIDE + ck0 * 16;
    const uint32_t dB = saB + rowL * STRIDE + ck0 * 16;

    const int nk = K / 32;

    auto load_stage = [&](int kt, int buf) {
        const bool ok = kt < nk;
        const int ko = ok ? kt * 32 : 0;
        const __half* pa = aBase + ko;
        const __half* pb = bBase + ko;
        cp16(dA + buf * STAGEB,      pa,     ok && aValid);
        cp16(dA + buf * STAGEB + 16, pa + 8, ok && aValid);
        cp16(dB + buf * STAGEB,      pb,     ok && bValid);
        cp16(dB + buf * STAGEB + 16, pb + 8, ok && bValid);
    };

    const int aoff = (wm + (lane & 15)) * STRIDE + (lane >> 4) * 16;
    const int boff = (wn + (lane & 7))  * STRIDE + ((lane >> 3) & 1) * 16;

    auto compute = [&](int buf) {
        const uint32_t sa = saA + buf * STAGEB;
        const uint32_t sb = saB + buf * STAGEB;
        #pragma unroll
        for (int ks = 0; ks < 2; ks++) {
            uint32_t af[4][4], bf[4][2];
            #pragma unroll
            for (int mt = 0; mt < 4; mt++)
                LDSM_X4(af[mt], sa + aoff + mt * 16 * STRIDE + ks * 32);
            #pragma unroll
            for (int nt = 0; nt < 4; nt++)
                LDSM_X2(bf[nt], sb + boff + nt * 8 * STRIDE + ks * 32);
            #pragma unroll
            for (int mt = 0; mt < 4; mt++)
                #pragma unroll
                for (int nt = 0; nt < 4; nt++)
                    asm volatile(
                        "mma.sync.aligned.m16n8k16.row.col.f32.f16.f16.f32 "
                        "{%0,%1,%2,%3}, {%4,%5,%6,%7}, {%8,%9}, {%0,%1,%2,%3};"
                        : "+f"(acc[mt][nt][0]), "+f"(acc[mt][nt][1]),
                          "+f"(acc[mt][nt][2]), "+f"(acc[mt][nt][3])
                        : "r"(af[mt][0]), "r"(af[mt][1]), "r"(af[mt][2]), "r"(af[mt][3]),
                          "r"(bf[nt][0]), "r"(bf[nt][1]));
        }
    };

    #pragma unroll
    for (int s = 0; s < STAGES - 1; s++) {
        load_stage(s, s);
        CP_COMMIT();
    }

    for (int kt = 0; kt < nk; kt++) {
        CP_WAIT2();
        __syncthreads();
        if (kt + STAGES - 1 < nk) load_stage(kt + STAGES - 1, (kt + STAGES - 1) & 3);
        CP_COMMIT();
        compute(kt & 3);
    }

    // ---- epilogue
    #pragma unroll
    for (int mt = 0; mt < 4; mt++) {
        const int r0 = m0 + wm + mt * 16 + grp;
        #pragma unroll
        for (int half = 0; half < 2; half++) {
            const int gm = r0 + half * 8;
            if (gm >= M) continue;
            #pragma unroll
            for (int nt = 0; nt < 4; nt++) {
                const int gn = n0 + wn + nt * 8 + idx * 2;
                if (gn >= N) continue;
                float v0 = acc[mt][nt][half * 2 + 0];
                float v1 = acc[mt][nt][half * 2 + 1];
                if (HAS_BIAS) { v0 += bias[gn]; v1 += bias[gn + 1]; }
                if (DO_GELU)  { v0 = gelu_exact(v0); v1 = gelu_exact(v1); }
                if (OUT_MODE == 2) {
                    // vT[b, h, d, s]: gm = token, gn = h*64+d
                    const int vb = gm / S_, vs = gm % S_;
                    const int vh = gn >> 6, vd = gn & 63;
                    __half* p = Ch + (((size_t)vb * H_ + vh) * HD_ + vd) * SP_ + vs;
                    p[0]   = __float2half(v0);
                    p[SP_] = __float2half(v1);
                } else if (OUT_MODE == 1) {
                    *reinterpret_cast<__half2*>(Ch + cOff + (size_t)gm * ldc + gn) =
                        __floats2half2_rn(v0, v1);
                } else {
                    float* p = C + cOff + (size_t)gm * ldc + gn;
                    if (ACCUM) {
                        float2 old = *reinterpret_cast<float2*>(p);
                        v0 += old.x; v1 += old.y;
                    }
                    *reinterpret_cast<float2*>(p) = make_float2(v0, v1);
                }
            }
        }
    }
}

// ---------------- weight transpose to fp16 ----------------
__global__ void transpose_h_kernel(const float* __restrict__ in, __half* __restrict__ out,
                                   int R, int Cc)
{
    __shared__ float tile[32][33];
    const size_t li = (size_t)blockIdx.z * R * Cc;
    const int c0 = blockIdx.x * 32, r0 = blockIdx.y * 32;
    const int x = threadIdx.x, y = threadIdx.y;
    #pragma unroll
    for (int j = 0; j < 32; j += 8)
        tile[y + j][x] = in[li + (size_t)(r0 + y + j) * Cc + c0 + x];
    __syncthreads();
    #pragma unroll
    for (int j = 0; j < 32; j += 8)
        out[li + (size_t)(c0 + y + j) * R + r0 + x] = __float2half(tile[x][y + j]);
}

__global__ void convw_h_kernel(const float* __restrict__ in, __half* __restrict__ out)
{
    int i = blockIdx.x * 256 + threadIdx.x;
    if (i < W_ * W_) out[i] = __float2half(in[i]);
}

// ---------------- im2col (fp16) ----------------
__global__ void im2col_kernel(const float* __restrict__ x, __half* __restrict__ out)
{
    const int total = B_ * NPATCH_ * W_;
    int idx = blockIdx.x * 256 + threadIdx.x;
    if (idx >= total) return;
    const int kk = idx % W_;
    const int r  = idx / W_;
    const int b  = r / NPATCH_;
    const int p  = r % NPATCH_;
    const int ph = p / 14, pw = p % 14;
    const int c  = kk >> 8;
    const int py = (kk >> 4) & 15;
    const int px = kk & 15;
    out[idx] = __float2half(
        x[(((size_t)b * C_ + c) * IMG_ + ph * P_ + py) * IMG_ + pw * P_ + px]);
}

// ---------------- assemble ----------------
__global__ void assemble_kernel(const float* __restrict__ tok,
                                const float* __restrict__ cls,
                                const float* __restrict__ pe,
                                float* __restrict__ h)
{
    int idx = blockIdx.x * 256 + threadIdx.x;
    if (idx >= BSW_) return;
    const int w  = idx % W_;
    const int bs = idx / W_;
    const int s  = bs % S_;
    const int b  = bs / S_;
    float v = (s == 0) ? cls[w] : tok[((size_t)b * NPATCH_ + (s - 1)) * W_ + w];
    h[idx] = v + pe[(size_t)s * W_ + w];
}

// ---------------- layernorm (fp32 in, fp16 out) ----------------
__global__ void layernorm_kernel(const float* __restrict__ x,
                                 const float* __restrict__ gamma,
                                 const float* __restrict__ beta,
                                 __half* __restrict__ y)
{
    const int row = blockIdx.x;
    const float* xr = x + (size_t)row * W_;
    float s = 0.f, s2 = 0.f;
    for (int i = threadIdx.x; i < W_; i += 256) {
        float v = xr[i];
        s += v; s2 += v * v;
    }
    for (int off = 16; off > 0; off >>= 1) {
        s  += __shfl_down_sync(0xffffffffu, s, off);
        s2 += __shfl_down_sync(0xffffffffu, s2, off);
    }
    __shared__ float rs[8], rs2[8];
    const int warp = threadIdx.x >> 5, lane = threadIdx.x & 31;
    if (lane == 0) { rs[warp] = s; rs2[warp] = s2; }
    __syncthreads();
    __shared__ float mean_sh, inv_sh;
    if (threadIdx.x == 0) {
        float ts = 0.f, ts2 = 0.f;
        for (int i = 0; i < 8; i++) { ts += rs[i]; ts2 += rs2[i]; }
        float mean = ts * (1.0f / W_);
        float var  = ts2 * (1.0f / W_) - mean * mean;
        mean_sh = mean;
        inv_sh  = rsqrtf(var + 1e-5f);
    }
    __syncthreads();
    const float mean = mean_sh, inv = inv_sh;
    __half* yr = y + (size_t)row * W_;
    for (int i = threadIdx.x; i < W_; i += 256)
        yr[i] = __float2half((xr[i] - mean) * inv * gamma[i] + beta[i]);
}

// ---------------- softmax: att f32 (ld 256) -> att_h f16 (ld 224, zero tail) ----------------
__global__ void softmax_kernel(const float* __restrict__ att, __half* __restrict__ atth,
                               int nrows)
{
    const int row = blockIdx.x * 4 + (threadIdx.x >> 5);
    const int lane = threadIdx.x & 31;
    if (row >= nrows) return;
    const float* in = att + (size_t)row * ALD_;
    __half* outp = atth + (size_t)row * SP_;

    float mx = -1e30f;
    for (int i = lane; i < S_; i += 32) mx = fmaxf(mx, in[i]);
    for (int off = 16; off > 0; off >>= 1)
        mx = fmaxf(mx, __shfl_xor_sync(0xffffffffu, mx, off));

    float e[7];
    float sum = 0.f;
    int c = 0;
    for (int i = lane; i < S_; i += 32, c++) {
        e[c] = expf((in[i] - mx) * 0.125f);
        sum += e[c];
    }
    for (int off = 16; off > 0; off >>= 1)
        sum += __shfl_xor_sync(0xffffffffu, sum, off);
    const float inv = 1.0f / sum;
    c = 0;
    for (int i = lane; i < SP_; i += 32, c++)
        outp[i] = __float2half(i < S_ ? e[c] * inv : 0.f);
}

// ---------------- gather / l2norm ----------------
__global__ void gather_cls_kernel(const float* __restrict__ h, __half* __restrict__ cls)
{
    int idx = blockIdx.x * 256 + threadIdx.x;
    if (idx >= B_ * W_) return;
    const int b = idx / W_, w = idx % W_;
    cls[idx] = __float2half(h[(size_t)b * S_ * W_ + w]);
}

__global__ void l2norm_kernel(float* __restrict__ out)
{
    const int row = blockIdx.x;
    float* r = out + (size_t)row * E_;
    float s = 0.f;
    for (int i = threadIdx.x; i < E_; i += 256) { float v = r[i]; s += v * v; }
    for (int off = 16; off > 0; off >>= 1) s += __shfl_down_sync(0xffffffffu, s, off);
    __shared__ float rs[8];
    const int warp = threadIdx.x >> 5, lane = threadIdx.x & 31;
    if (lane == 0) rs[warp] = s;
    __syncthreads();
    __shared__ float inv_sh;
    if (threadIdx.x == 0) {
        float ts = 0.f;
        for (int i = 0; i < 8; i++) ts += rs[i];
        inv_sh = rsqrtf(ts);
    }
    __syncthreads();
    const float inv = inv_sh;
    for (int i = threadIdx.x; i < E_; i += 256) r[i] *= inv;
}

// ---------------- launch ----------------
extern "C" void kernel_launch(void* const* d_in, const int* in_sizes, int n_in,
                              void* d_out, int out_size)
{
    (void)in_sizes; (void)n_in; (void)out_size;

    const float* x       = (const float*)d_in[0];
    const float* conv_w  = (const float*)d_in[1];
    const float* conv_b  = (const float*)d_in[2];
    const float* cls_tok = (const float*)d_in[3];
    const float* pe      = (const float*)d_in[4];
    const float* ln1_g   = (const float*)d_in[5];
    const float* ln1_b   = (const float*)d_in[6];
    const float* wq      = (const float*)d_in[7];
    const float* bq      = (const float*)d_in[8];
    const float* wk      = (const float*)d_in[9];
    const float* bk      = (const float*)d_in[10];
    const float* wv      = (const float*)d_in[11];
    const float* bv      = (const float*)d_in[12];
    const float* wo      = (const float*)d_in[13];
    const float* bo      = (const float*)d_in[14];
    const float* ln2_g   = (const float*)d_in[15];
    const float* ln2_b   = (const float*)d_in[16];
    const float* w1      = (const float*)d_in[17];
    const float* b1      = (const float*)d_in[18];
    const float* w2      = (const float*)d_in[19];
    const float* b2      = (const float*)d_in[20];
    const float* proj    = (const float*)d_in[21];
    float* out           = (float*)d_out;

    float  *h, *att, *tok;
    __half *y, *qh, *kh, *vT, *o, *atth, *ff, *i2c, *cls, *convw16;
    __half *wqT, *wkT, *wvT, *woT, *w1T, *w2T, *projT;
    cudaGetSymbolAddress((void**)&h,    g_h);
    cudaGetSymbolAddress((void**)&y,    g_y);
    cudaGetSymbolAddress((void**)&qh,   g_qh);
    cudaGetSymbolAddress((void**)&kh,   g_kh);
    cudaGetSymbolAddress((void**)&vT,   g_vT);
    cudaGetSymbolAddress((void**)&o,    g_o);
    cudaGetSymbolAddress((void**)&att,  g_att);
    cudaGetSymbolAddress((void**)&atth, g_atth);
    cudaGetSymbolAddress((void**)&ff,   g_ff);
    cudaGetSymbolAddress((void**)&i2c,  g_im2col);
    cudaGetSymbolAddress((void**)&tok,  g_tok);
    cudaGetSymbolAddress((void**)&cls,  g_cls);
    cudaGetSymbolAddress((void**)&convw16, g_convw16);
    cudaGetSymbolAddress((void**)&wqT,  g_wqT);
    cudaGetSymbolAddress((void**)&wkT,  g_wkT);
    cudaGetSymbolAddress((void**)&wvT,  g_wvT);
    cudaGetSymbolAddress((void**)&woT,  g_woT);
    cudaGetSymbolAddress((void**)&w1T,  g_w1T);
    cudaGetSymbolAddress((void**)&w2T,  g_w2T);
    cudaGetSymbolAddress((void**)&projT, g_projT);

    cudaFuncSetAttribute(gemm_f16<1,0,0,0>, cudaFuncAttributeMaxDynamicSharedMemorySize, GEMM_SMEM);
    cudaFuncSetAttribute(gemm_f16<1,0,0,1>, cudaFuncAttributeMaxDynamicSharedMemorySize, GEMM_SMEM);
    cudaFuncSetAttribute(gemm_f16<1,0,0,2>, cudaFuncAttributeMaxDynamicSharedMemorySize, GEMM_SMEM);
    cudaFuncSetAttribute(gemm_f16<0,0,0,0>, cudaFuncAttributeMaxDynamicSharedMemorySize, GEMM_SMEM);
    cudaFuncSetAttribute(gemm_f16<0,0,0,1>, cudaFuncAttributeMaxDynamicSharedMemorySize, GEMM_SMEM);
    cudaFuncSetAttribute(gemm_f16<1,1,0,0>, cudaFuncAttributeMaxDynamicSharedMemorySize, GEMM_SMEM);
    cudaFuncSetAttribute(gemm_f16<1,0,1,1>, cudaFuncAttributeMaxDynamicSharedMemorySize, GEMM_SMEM);

    const int M  = B_ * S_;       // 6304
    const int Mp = B_ * NPATCH_;  // 6272
    dim3 blkT(32, 8);

    cudaMemsetAsync(vT, 0, (size_t)B_ * H_ * HD_ * SP_ * sizeof(__half), 0);

    im2col_kernel<<<(Mp * W_ + 255) / 256, 256>>>(x, i2c);
    convw_h_kernel<<<(W_ * W_ + 255) / 256, 256>>>(conv_w, convw16);
    transpose_h_kernel<<<dim3(FF_/32, W_/32,  L_), blkT>>>(w1, w1T, W_, FF_);
    transpose_h_kernel<<<dim3(W_/32,  FF_/32, L_), blkT>>>(w2, w2T, FF_, W_);
    transpose_h_kernel<<<dim3(W_/32,  W_/32,  L_), blkT>>>(wq, wqT, W_, W_);
    transpose_h_kernel<<<dim3(W_/32,  W_/32,  L_), blkT>>>(wk, wkT, W_, W_);
    transpose_h_kernel<<<dim3(W_/32,  W_/32,  L_), blkT>>>(wv, wvT, W_, W_);
    transpose_h_kernel<<<dim3(W_/32,  W_/32,  L_), blkT>>>(wo, woT, W_, W_);
    transpose_h_kernel<<<dim3(E_/32,  W_/32,  1),  blkT>>>(proj, projT, W_, E_);

    {   // patch embed GEMM -> tok (f32)
        dim3 grid(W_ / 128, (Mp + 127) / 128, 1);
        gemm_f16<1,0,0,0><<<grid, 256, GEMM_SMEM>>>(i2c, convw16, conv_b, tok, nullptr,
            Mp, W_, W_, W_, W_, W_, 0,0,0,0,0,0);
    }
    assemble_kernel<<<(BSW_ + 255) / 256, 256>>>(tok, cls_tok, pe, h);

    const int nrows_att = B_ * H_ * S_;
    dim3 gridW (W_  / 128, (M + 127) / 128, 1);
    dim3 gridFF(FF_ / 128, (M + 127) / 128, 1);
    dim3 gridSc(2, 2, B_ * H_);
    dim3 gridAv(1, 2, B_ * H_);

    const long long qBs = (long long)S_ * W_;     // per-batch stride in q/k
    const long long aZb = (long long)H_ * S_ * ALD_, aZh = (long long)S_ * ALD_;
    const long long ahZb = (long long)H_ * S_ * SP_, ahZh = (long long)S_ * SP_;
    const long long vZb = (long long)H_ * HD_ * SP_, vZh = (long long)HD_ * SP_;
    const long long oBs = (long long)S_ * W_;

    for (int l = 0; l < L_; l++) {
        const size_t wOff = (size_t)l * W_ * W_;
        const size_t bOff = (size_t)l * W_;

        layernorm_kernel<<<M, 256>>>(h, ln1_g + bOff, ln1_b + bOff, y);
        gemm_f16<1,0,0,1><<<gridW, 256, GEMM_SMEM>>>(y, wqT + wOff, bq + bOff, nullptr, qh,
            M, W_, W_, W_, W_, W_, 0,0,0,0,0,0);
        gemm_f16<1,0,0,1><<<gridW, 256, GEMM_SMEM>>>(y, wkT + wOff, bk + bOff, nullptr, kh,
            M, W_, W_, W_, W_, W_, 0,0,0,0,0,0);
        gemm_f16<1,0,0,2><<<gridW, 256, GEMM_SMEM>>>(y, wvT + wOff, bv + bOff, nullptr, vT,
            M, W_, W_, W_, W_, W_, 0,0,0,0,0,0);
        // scores: att[z, s, t] = q . k
        gemm_f16<0,0,0,0><<<gridSc, 256, GEMM_SMEM>>>(qh, kh, nullptr, att, nullptr,
            S_, S_, HD_, W_, W_, ALD_,
            qBs, (long long)HD_, qBs, (long long)HD_, aZb, aZh);
        softmax_kernel<<<(nrows_att + 3) / 4, 128>>>(att, atth, nrows_att);
        // AV: o[b, s, h*64+d] = att_h @ vT^T
        gemm_f16<0,0,0,1><<<gridAv, 256, GEMM_SMEM>>>(atth, vT, nullptr, nullptr, o,
            S_, HD_, SP_, SP_, SP_, W_,
            ahZb, ahZh, vZb, vZh, oBs, (long long)HD_);
        gemm_f16<1,1,0,0><<<gridW, 256, GEMM_SMEM>>>(o, woT + wOff, bo + bOff, h, nullptr,
            M, W_, W_, W_, W_, W_, 0,0,0,0,0,0);
        layernorm_kernel<<<M, 256>>>(h, ln2_g + bOff, ln2_b + bOff, y);
        gemm_f16<1,0,1,1><<<gridFF, 256, GEMM_SMEM>>>(y, w1T + (size_t)l * W_ * FF_,
            b1 + (size_t)l * FF_, nullptr, ff,
            M, FF_, W_, W_, W_, FF_, 0,0,0,0,0,0);
        gemm_f16<1,1,0,0><<<gridW, 256, GEMM_SMEM>>>(ff, w2T + (size_t)l * FF_ * W_,
            b2 + bOff, h, nullptr,
            M, W_, FF_, FF_, FF_, W_, 0,0,0,0,0,0);
    }

    gather_cls_kernel<<<(B_ * W_ + 255) / 256, 256>>>(h, cls);
    {
        dim3 grid(E_ / 128, 1, 1);
        gemm_f16<0,0,0,0><<<grid, 256, GEMM_SMEM>>>(cls, projT, nullptr, out, nullptr,
            B_, E_, W_, W_, W_, E_, 0,0,0,0,0,0);
    }
    l2norm_kernel<<<B_, 256>>>(out);
}

// round 8
// speedup vs baseline: 2.6860x; 1.0880x over previous
#include <cuda_runtime.h>
#include <cuda_fp16.h>
#include <math.h>
#include <stdint.h>

// ---------------- problem constants ----------------
#define B_  32
#define C_  3
#define IMG_ 224
#define P_  16
#define W_  768
#define L_  12
#define H_  12
#define S_  197
#define HD_ 64
#define FF_ 3072
#define E_  512
#define NPATCH_ 196
#define BSW_ (B_*S_*W_)
#define SP_ 224
#define ALD_ 256
#define QKV_ 2304

// ---------------- scratch ----------------
__device__ float  g_h   [BSW_];
__device__ __half g_y   [BSW_];
__device__ __half g_qh  [BSW_];
__device__ __half g_kh  [BSW_];
__device__ __half g_vT  [B_*H_*HD_*SP_];
__device__ __half g_o   [BSW_];
__device__ float  g_att [B_*H_*S_*ALD_];
__device__ __half g_atth[B_*H_*S_*SP_];
__device__ __half g_ff  [B_*S_*FF_];
__device__ __half g_im2col[B_*NPATCH_*W_];
__device__ float  g_tok [B_*NPATCH_*W_];
__device__ __half g_cls [B_*W_];
__device__ __half g_convw16[W_*W_];
__device__ __half g_wqkvT[L_*QKV_*W_];
__device__ float  g_bqkv [L_*QKV_];
__device__ __half g_woT [L_*W_*W_];
__device__ __half g_w1T [L_*W_*FF_];
__device__ __half g_w2T [L_*FF_*W_];
__device__ __half g_projT[W_*E_];

__device__ __forceinline__ float gelu_exact(float v) {
    return 0.5f * v * (1.0f + erff(v * 0.70710678118654752f));
}
__device__ __forceinline__ uint32_t smem_u32(const void* p) {
    uint32_t a;
    asm("{ .reg .u64 t; cvta.to.shared.u64 t, %1; cvt.u32.u64 %0, t; }" : "=r"(a) : "l"(p));
    return a;
}

#define LDSM_X4(r, addr) \
    asm volatile("ldmatrix.sync.aligned.m8n8.x4.shared.b16 {%0,%1,%2,%3}, [%4];" \
        : "=r"((r)[0]), "=r"((r)[1]), "=r"((r)[2]), "=r"((r)[3]) : "r"(addr))
#define LDSM_X2(r, addr) \
    asm volatile("ldmatrix.sync.aligned.m8n8.x2.shared.b16 {%0,%1}, [%2];" \
        : "=r"((r)[0]), "=r"((r)[1]) : "r"(addr))

__device__ __forceinline__ void cp16(uint32_t dst, const void* src, bool valid) {
    int sz = valid ? 16 : 0;
    asm volatile("cp.async.cg.shared.global [%0], [%1], 16, %2;"
                 :: "r"(dst), "l"(src), "r"(sz));
}
#define CP_COMMIT() asm volatile("cp.async.commit_group;" ::: "memory")
#define CP_WAIT2()  asm volatile("cp.async.wait_group 2;" ::: "memory")

#define MMA16816(acc, af, bf) \
    asm volatile("mma.sync.aligned.m16n8k16.row.col.f32.f16.f16.f32 " \
        "{%0,%1,%2,%3}, {%4,%5,%6,%7}, {%8,%9}, {%0,%1,%2,%3};" \
        : "+f"((acc)[0]), "+f"((acc)[1]), "+f"((acc)[2]), "+f"((acc)[3]) \
        : "r"((af)[0]), "r"((af)[1]), "r"((af)[2]), "r"((af)[3]), \
          "r"((bf)[0]), "r"((bf)[1]))

// =====================================================================
// WIDE GEMM: 128x256 CTA tile, 512 threads (16 warps x 64x32), KT=32,
// 4-stage cp.async. C[M,N] = A[M,K] @ Bt[N,K]^T. Batched over grid.z.
// OUT_MODE: 0 = f32 C (opt ACCUM/bias), 1 = f16 Ch (opt gelu), 3 = QKV route.
// =====================================================================
#define WSTRIDE 80
#define ASTG (128 * WSTRIDE)              // 10240
#define BSTG (256 * WSTRIDE)              // 20480
#define WSMEM (4 * (ASTG + BSTG))         // 122880

template<int HAS_BIAS, int ACCUM, int DO_GELU, int OUT_MODE>
__global__ __launch_bounds__(512)
void gemm_wide(const __half* __restrict__ A, const __half* __restrict__ Bt,
               const float* __restrict__ bias, float* __restrict__ C,
               __half* __restrict__ Ch, __half* __restrict__ Kh,
               __half* __restrict__ Vt,
               int M, int N, int K, int lda, int ldb, int ldc,
               long long aBs, long long aHs, long long bBs, long long bHs,
               long long cBs, long long cHs)
{
    extern __shared__ __align__(128) uint8_t sm[];
    uint8_t* smA = sm;
    uint8_t* smB = sm + 4 * ASTG;

    const int z = blockIdx.z;
    const int zb = z / H_, zh = z % H_;
    A  += (size_t)zb * aBs + (size_t)zh * aHs;
    Bt += (size_t)zb * bBs + (size_t)zh * bHs;
    const long long cOff = (long long)zb * cBs + (long long)zh * cHs;

    const int t    = threadIdx.x;
    const int warp = t >> 5, lane = t & 31;
    const int m0   = blockIdx.y * 128;
    const int n0   = blockIdx.x * 256;
    const int wm   = (warp >> 3) * 64;    // 0 or 64
    const int wn   = (warp & 7) * 32;     // 0..224
    const int grp  = lane >> 2;
    const int idx  = lane & 3;

    float acc[4][4][4];
    #pragma unroll
    for (int a = 0; a < 4; a++)
        #pragma unroll
        for (int b = 0; b < 4; b++)
            #pragma unroll
            for (int c = 0; c < 4; c++) acc[a][b][c] = 0.0f;

    const uint32_t saA = smem_u32(smA);
    const uint32_t saB = smem_u32(smB);

    // cp.async mapping (512 thr): A 128rows x 64B -> 1 chunk/thr; B 256rows -> 2.
    const int rowX = t >> 2;        // 0..127
    const int ck   = t & 3;         // 16B chunk
    const bool aValid  = (m0 + rowX) < M;
    const bool bValid0 = (n0 + rowX) < N;
    const bool bValid1 = (n0 + rowX + 128) < N;
    const __half* aBase  = A  + (size_t)(m0 + rowX) * lda + ck * 8;
    const __half* bBase0 = Bt + (size_t)(n0 + rowX) * ldb + ck * 8;
    const __half* bBase1 = Bt + (size_t)(n0 + rowX + 128) * ldb + ck * 8;
    const uint32_t dA  = saA + rowX * WSTRIDE + ck * 16;
    const uint32_t dB0 = saB + rowX * WSTRIDE + ck * 16;
    const uint32_t dB1 = saB + (rowX + 128) * WSTRIDE + ck * 16;

    const int nk = K / 32;

    auto load_stage = [&](int kt, int buf) {
        const bool ok = kt < nk;
        const int ko = ok ? kt * 32 : 0;
        cp16(dA  + buf * ASTG, aBase  + ko, ok && aValid);
        cp16(dB0 + buf * BSTG, bBase0 + ko, ok && bValid0);
        cp16(dB1 + buf * BSTG, bBase1 + ko, ok && bValid1);
    };

    const int aoff = (wm + (lane & 15)) * WSTRIDE + (lane >> 4) * 16;
    const int boff = (wn + (lane & 7))  * WSTRIDE + ((lane >> 3) & 1) * 16;

    auto compute = [&](int buf) {
        const uint32_t sa = saA + buf * ASTG;
        const uint32_t sb = saB + buf * BSTG;
        #pragma unroll
        for (int ks = 0; ks < 2; ks++) {
            uint32_t af[4][4], bf[4][2];
            #pragma unroll
            for (int mt = 0; mt < 4; mt++)
                LDSM_X4(af[mt], sa + aoff + mt * 16 * WSTRIDE + ks * 32);
            #pragma unroll
            for (int nt = 0; nt < 4; nt++)
                LDSM_X2(bf[nt], sb + boff + nt * 8 * WSTRIDE + ks * 32);
            #pragma unroll
            for (int mt = 0; mt < 4; mt++)
                #pragma unroll
                for (int nt = 0; nt < 4; nt++)
                    MMA16816(acc[mt][nt], af[mt], bf[nt]);
        }
    };

    #pragma unroll
    for (int s = 0; s < 3; s++) {
        load_stage(s, s);
        CP_COMMIT();
    }

    for (int kt = 0; kt < nk; kt++) {
        CP_WAIT2();
        __syncthreads();
        load_stage(kt + 3, (kt + 3) & 3);
        CP_COMMIT();
        compute(kt & 3);
    }

    // ---- epilogue
    #pragma unroll
    for (int mt = 0; mt < 4; mt++) {
        const int r0 = m0 + wm + mt * 16 + grp;
        #pragma unroll
        for (int half = 0; half < 2; half++) {
            const int gm = r0 + half * 8;
            if (gm >= M) continue;
            #pragma unroll
            for (int nt = 0; nt < 4; nt++) {
                const int gn = n0 + wn + nt * 8 + idx * 2;
                if (gn >= N) continue;
                float v0 = acc[mt][nt][half * 2 + 0];
                float v1 = acc[mt][nt][half * 2 + 1];
                if (HAS_BIAS) { v0 += bias[gn]; v1 += bias[gn + 1]; }
                if (DO_GELU)  { v0 = gelu_exact(v0); v1 = gelu_exact(v1); }
                if (OUT_MODE == 3) {
                    if (gn < W_) {
                        *reinterpret_cast<__half2*>(Ch + (size_t)gm * W_ + gn) =
                            __floats2half2_rn(v0, v1);
                    } else if (gn < 2 * W_) {
                        *reinterpret_cast<__half2*>(Kh + (size_t)gm * W_ + gn - W_) =
                            __floats2half2_rn(v0, v1);
                    } else {
                        const int col = gn - 2 * W_;
                        const int vh = col >> 6, vd = col & 63;
                        const int vb = gm / S_, vs = gm % S_;
                        __half* p = Vt + (((size_t)vb * H_ + vh) * HD_ + vd) * SP_ + vs;
                        p[0]   = __float2half(v0);
                        p[SP_] = __float2half(v1);
                    }
                } else if (OUT_MODE == 1) {
                    *reinterpret_cast<__half2*>(Ch + cOff + (size_t)gm * ldc + gn) =
                        __floats2half2_rn(v0, v1);
                } else {
                    float* p = C + cOff + (size_t)gm * ldc + gn;
                    if (ACCUM) {
                        float2 old = *reinterpret_cast<float2*>(p);
                        v0 += old.x; v1 += old.y;
                    }
                    *reinterpret_cast<float2*>(p) = make_float2(v0, v1);
                }
            }
        }
    }
}

// =====================================================================
// NARROW GEMM (AV): 128x128 tile, 256 threads, as round 7.
// =====================================================================
#define STRIDE 80
#define STAGEB (128 * STRIDE)
#define GEMM_SMEM (8 * STAGEB)   // 81920

__global__ __launch_bounds__(256)
void gemm_av(const __half* __restrict__ A, const __half* __restrict__ Bt,
             __half* __restrict__ Ch, int M, int N, int K,
             int lda, int ldb, int ldc,
             long long aBs, long long aHs, long long bBs, long long bHs,
             long long cBs, long long cHs)
{
    extern __shared__ __align__(128) uint8_t sm[];
    uint8_t* smA = sm;
    uint8_t* smB = sm + 4 * STAGEB;

    const int z = blockIdx.z;
    const int zb = z / H_, zh = z % H_;
    A  += (size_t)zb * aBs + (size_t)zh * aHs;
    Bt += (size_t)zb * bBs + (size_t)zh * bHs;
    const long long cOff = (long long)zb * cBs + (long long)zh * cHs;

    const int t    = threadIdx.x;
    const int warp = t >> 5, lane = t & 31;
    const int m0   = blockIdx.y * 128;
    const int n0   = blockIdx.x * 128;
    const int wm   = (warp >> 2) * 64;
    const int wn   = (warp & 3) * 32;
    const int grp  = lane >> 2;
    const int idx  = lane & 3;

    float acc[4][4][4];
    #pragma unroll
    for (int a = 0; a < 4; a++)
        #pragma unroll
        for (int b = 0; b < 4; b++)
            #pragma unroll
            for (int c = 0; c < 4; c++) acc[a][b][c] = 0.0f;

    const uint32_t saA = smem_u32(smA);
    const uint32_t saB = smem_u32(smB);

    const int rowL = t >> 1;
    const int ck0  = (t & 1) * 2;
    const bool aValid = (m0 + rowL) < M;
    const bool bValid = (n0 + rowL) < N;
    const __half* aBase = A + (size_t)(m0 + rowL) * lda + ck0 * 8;
    const __half* bBase = Bt + (size_t)(n0 + rowL) * ldb + ck0 * 8;
    const uint32_t dA = saA + rowL * STRIDE + ck0 * 16;
    const uint32_t dB = saB + rowL * STRIDE + ck0 * 16;

    const int nk = K / 32;

    auto load_stage = [&](int kt, int buf) {
        const bool ok = kt < nk;
        const int ko = ok ? kt * 32 : 0;
        cp16(dA + buf * STAGEB,      aBase + ko,     ok && aValid);
        cp16(dA + buf * STAGEB + 16, aBase + ko + 8, ok && aValid);
        cp16(dB + buf * STAGEB,      bBase + ko,     ok && bValid);
        cp16(dB + buf * STAGEB + 16, bBase + ko + 8, ok && bValid);
    };

    const int aoff = (wm + (lane & 15)) * STRIDE + (lane >> 4) * 16;
    const int boff = (wn + (lane & 7))  * STRIDE + ((lane >> 3) & 1) * 16;

    auto compute = [&](int buf) {
        const uint32_t sa = saA + buf * STAGEB;
        const uint32_t sb = saB + buf * STAGEB;
        #pragma unroll
        for (int ks = 0; ks < 2; ks++) {
            uint32_t af[4][4], bf[4][2];
            #pragma unroll
            for (int mt = 0; mt < 4; mt++)
                LDSM_X4(af[mt], sa + aoff + mt * 16 * STRIDE + ks * 32);
            #pragma unroll
            for (int nt = 0; nt < 4; nt++)
                LDSM_X2(bf[nt], sb + boff + nt * 8 * STRIDE + ks * 32);
            #pragma unroll
            for (int mt = 0; mt < 4; mt++)
                #pragma unroll
                for (int nt = 0; nt < 4; nt++)
                    MMA16816(acc[mt][nt], af[mt], bf[nt]);
        }
    };

    #pragma unroll
    for (int s = 0; s < 3; s++) {
        load_stage(s, s);
        CP_COMMIT();
    }

    for (int kt = 0; kt < nk; kt++) {
        CP_WAIT2();
        __syncthreads();
        load_stage(kt + 3, (kt + 3) & 3);
        CP_COMMIT();
        compute(kt & 3);
    }

    #pragma unroll
    for (int mt = 0; mt < 4; mt++) {
        const int r0 = m0 + wm + mt * 16 + grp;
        #pragma unroll
        for (int half = 0; half < 2; half++) {
            const int gm = r0 + half * 8;
            if (gm >= M) continue;
            #pragma unroll
            for (int nt = 0; nt < 4; nt++) {
                const int gn = n0 + wn + nt * 8 + idx * 2;
                if (gn >= N) continue;
                *reinterpret_cast<__half2*>(Ch + cOff + (size_t)gm * ldc + gn) =
                    __floats2half2_rn(acc[mt][nt][half * 2 + 0],
                                      acc[mt][nt][half * 2 + 1]);
            }
        }
    }
}

// ---------------- transpose f32->f16, with strided/offset output ----------------
__global__ void transpose_h_kernel(const float* __restrict__ in, __half* __restrict__ out,
                                   int R, int Cc, long long ldOut, int rowOff)
{
    __shared__ float tile[32][33];
    const size_t li = (size_t)blockIdx.z * R * Cc;
    const int c0 = blockIdx.x * 32, r0 = blockIdx.y * 32;
    const int x = threadIdx.x, y = threadIdx.y;
    #pragma unroll
    for (int j = 0; j < 32; j += 8)
        tile[y + j][x] = in[li + (size_t)(r0 + y + j) * Cc + c0 + x];
    __syncthreads();
    #pragma unroll
    for (int j = 0; j < 32; j += 8)
        out[(size_t)blockIdx.z * ldOut + (size_t)(rowOff + c0 + y + j) * R + r0 + x] =
            __float2half(tile[x][y + j]);
}

__global__ void convw_h_kernel(const float* __restrict__ in, __half* __restrict__ out)
{
    int i = blockIdx.x * 256 + threadIdx.x;
    if (i < W_ * W_) out[i] = __float2half(in[i]);
}

__global__ void bias_concat_kernel(const float* __restrict__ bq, const float* __restrict__ bk,
                                   const float* __restrict__ bv, float* __restrict__ o)
{
    int i = blockIdx.x * 256 + threadIdx.x;
    if (i >= L_ * QKV_) return;
    const int l = i / QKV_, j = i % QKV_;
    float v = (j < W_) ? bq[l * W_ + j]
            : (j < 2 * W_) ? bk[l * W_ + j - W_]
            : bv[l * W_ + j - 2 * W_];
    o[i] = v;
}

// ---------------- im2col (fp16) ----------------
__global__ void im2col_kernel(const float* __restrict__ x, __half* __restrict__ out)
{
    const int total = B_ * NPATCH_ * W_;
    int idx = blockIdx.x * 256 + threadIdx.x;
    if (idx >= total) return;
    const int kk = idx % W_;
    const int r  = idx / W_;
    const int b  = r / NPATCH_;
    const int p  = r % NPATCH_;
    const int ph = p / 14, pw = p % 14;
    const int c  = kk >> 8;
    const int py = (kk >> 4) & 15;
    const int px = kk & 15;
    out[idx] = __float2half(
        x[(((size_t)b * C_ + c) * IMG_ + ph * P_ + py) * IMG_ + pw * P_ + px]);
}

// ---------------- assemble ----------------
__global__ void assemble_kernel(const float* __restrict__ tok,
                                const float* __restrict__ cls,
                                const float* __restrict__ pe,
                                float* __restrict__ h)
{
    int idx = blockIdx.x * 256 + threadIdx.x;
    if (idx >= BSW_) return;
    const int w  = idx % W_;
    const int bs = idx / W_;
    const int s  = bs % S_;
    const int b  = bs / S_;
    float v = (s == 0) ? cls[w] : tok[((size_t)b * NPATCH_ + (s - 1)) * W_ + w];
    h[idx] = v + pe[(size_t)s * W_ + w];
}

// ---------------- layernorm ----------------
__global__ void layernorm_kernel(const float* __restrict__ x,
                                 const float* __restrict__ gamma,
                                 const float* __restrict__ beta,
                                 __half* __restrict__ y)
{
    const int row = blockIdx.x;
    const float* xr = x + (size_t)row * W_;
    float s = 0.f, s2 = 0.f;
    for (int i = threadIdx.x; i < W_; i += 256) {
        float v = xr[i];
        s += v; s2 += v * v;
    }
    for (int off = 16; off > 0; off >>= 1) {
        s  += __shfl_down_sync(0xffffffffu, s, off);
        s2 += __shfl_down_sync(0xffffffffu, s2, off);
    }
    __shared__ float rs[8], rs2[8];
    const int warp = threadIdx.x >> 5, lane = threadIdx.x & 31;
    if (lane == 0) { rs[warp] = s; rs2[warp] = s2; }
    __syncthreads();
    __shared__ float mean_sh, inv_sh;
    if (threadIdx.x == 0) {
        float ts = 0.f, ts2 = 0.f;
        for (int i = 0; i < 8; i++) { ts += rs[i]; ts2 += rs2[i]; }
        float mean = ts * (1.0f / W_);
        float var  = ts2 * (1.0f / W_) - mean * mean;
        mean_sh = mean;
        inv_sh  = rsqrtf(var + 1e-5f);
    }
    __syncthreads();
    const float mean = mean_sh, inv = inv_sh;
    __half* yr = y + (size_t)row * W_;
    for (int i = threadIdx.x; i < W_; i += 256)
        yr[i] = __float2half((xr[i] - mean) * inv * gamma[i] + beta[i]);
}

// ---------------- softmax: f32 (ld 256) -> f16 (ld 224, zero tail) ----------------
__global__ void softmax_kernel(const float* __restrict__ att, __half* __restrict__ atth,
                               int nrows)
{
    const int row = blockIdx.x * 4 + (threadIdx.x >> 5);
    const int lane = threadIdx.x & 31;
    if (row >= nrows) return;
    const float* in = att + (size_t)row * ALD_;
    __half* outp = atth + (size_t)row * SP_;

    float mx = -1e30f;
    for (int i = lane; i < S_; i += 32) mx = fmaxf(mx, in[i]);
    for (int off = 16; off > 0; off >>= 1)
        mx = fmaxf(mx, __shfl_xor_sync(0xffffffffu, mx, off));

    float e[7];
    float sum = 0.f;
    int c = 0;
    for (int i = lane; i < S_; i += 32, c++) {
        e[c] = expf((in[i] - mx) * 0.125f);
        sum += e[c];
    }
    for (int off = 16; off > 0; off >>= 1)
        sum += __shfl_xor_sync(0xffffffffu, sum, off);
    const float inv = 1.0f / sum;
    c = 0;
    for (int i = lane; i < SP_; i += 32, c++)
        outp[i] = __float2half(i < S_ ? e[c] * inv : 0.f);
}

// ---------------- gather / l2norm ----------------
__global__ void gather_cls_kernel(const float* __restrict__ h, __half* __restrict__ cls)
{
    int idx = blockIdx.x * 256 + threadIdx.x;
    if (idx >= B_ * W_) return;
    const int b = idx / W_, w = idx % W_;
    cls[idx] = __float2half(h[(size_t)b * S_ * W_ + w]);
}

__global__ void l2norm_kernel(float* __restrict__ out)
{
    const int row = blockIdx.x;
    float* r = out + (size_t)row * E_;
    float s = 0.f;
    for (int i = threadIdx.x; i < E_; i += 256) { float v = r[i]; s += v * v; }
    for (int off = 16; off > 0; off >>= 1) s += __shfl_down_sync(0xffffffffu, s, off);
    __shared__ float rs[8];
    const int warp = threadIdx.x >> 5, lane = threadIdx.x & 31;
    if (lane == 0) rs[warp] = s;
    __syncthreads();
    __shared__ float inv_sh;
    if (threadIdx.x == 0) {
        float ts = 0.f;
        for (int i = 0; i < 8; i++) ts += rs[i];
        inv_sh = rsqrtf(ts);
    }
    __syncthreads();
    const float inv = inv_sh;
    for (int i = threadIdx.x; i < E_; i += 256) r[i] *= inv;
}

// ---------------- launch ----------------
extern "C" void kernel_launch(void* const* d_in, const int* in_sizes, int n_in,
                              void* d_out, int out_size)
{
    (void)in_sizes; (void)n_in; (void)out_size;

    const float* x       = (const float*)d_in[0];
    const float* conv_w  = (const float*)d_in[1];
    const float* conv_b  = (const float*)d_in[2];
    const float* cls_tok = (const float*)d_in[3];
    const float* pe      = (const float*)d_in[4];
    const float* ln1_g   = (const float*)d_in[5];
    const float* ln1_b   = (const float*)d_in[6];
    const float* wq      = (const float*)d_in[7];
    const float* bq      = (const float*)d_in[8];
    const float* wk      = (const float*)d_in[9];
    const float* bk      = (const float*)d_in[10];
    const float* wv      = (const float*)d_in[11];
    const float* bv      = (const float*)d_in[12];
    const float* wo      = (const float*)d_in[13];
    const float* bo      = (const float*)d_in[14];
    const float* ln2_g   = (const float*)d_in[15];
    const float* ln2_b   = (const float*)d_in[16];
    const float* w1      = (const float*)d_in[17];
    const float* b1      = (const float*)d_in[18];
    const float* w2      = (const float*)d_in[19];
    const float* b2      = (const float*)d_in[20];
    const float* proj    = (const float*)d_in[21];
    float* out           = (float*)d_out;

    float  *h, *att, *tok, *bqkv;
    __half *y, *qh, *kh, *vT, *o, *atth, *ff, *i2c, *cls, *convw16;
    __half *wqkvT, *woT, *w1T, *w2T, *projT;
    cudaGetSymbolAddress((void**)&h,    g_h);
    cudaGetSymbolAddress((void**)&y,    g_y);
    cudaGetSymbolAddress((void**)&qh,   g_qh);
    cudaGetSymbolAddress((void**)&kh,   g_kh);
    cudaGetSymbolAddress((void**)&vT,   g_vT);
    cudaGetSymbolAddress((void**)&o,    g_o);
    cudaGetSymbolAddress((void**)&att,  g_att);
    cudaGetSymbolAddress((void**)&atth, g_atth);
    cudaGetSymbolAddress((void**)&ff,   g_ff);
    cudaGetSymbolAddress((void**)&i2c,  g_im2col);
    cudaGetSymbolAddress((void**)&tok,  g_tok);
    cudaGetSymbolAddress((void**)&cls,  g_cls);
    cudaGetSymbolAddress((void**)&convw16, g_convw16);
    cudaGetSymbolAddress((void**)&wqkvT, g_wqkvT);
    cudaGetSymbolAddress((void**)&bqkv,  g_bqkv);
    cudaGetSymbolAddress((void**)&woT,  g_woT);
    cudaGetSymbolAddress((void**)&w1T,  g_w1T);
    cudaGetSymbolAddress((void**)&w2T,  g_w2T);
    cudaGetSymbolAddress((void**)&projT, g_projT);

    cudaFuncSetAttribute(gemm_wide<1,0,0,0>, cudaFuncAttributeMaxDynamicSharedMemorySize, WSMEM);
    cudaFuncSetAttribute(gemm_wide<1,0,0,3>, cudaFuncAttributeMaxDynamicSharedMemorySize, WSMEM);
    cudaFuncSetAttribute(gemm_wide<0,0,0,0>, cudaFuncAttributeMaxDynamicSharedMemorySize, WSMEM);
    cudaFuncSetAttribute(gemm_wide<1,1,0,0>, cudaFuncAttributeMaxDynamicSharedMemorySize, WSMEM);
    cudaFuncSetAttribute(gemm_wide<1,0,1,1>, cudaFuncAttributeMaxDynamicSharedMemorySize, WSMEM);
    cudaFuncSetAttribute(gemm_av, cudaFuncAttributeMaxDynamicSharedMemorySize, GEMM_SMEM);

    const int M  = B_ * S_;       // 6304
    const int Mp = B_ * NPATCH_;  // 6272
    dim3 blkT(32, 8);

    cudaMemsetAsync(vT, 0, (size_t)B_ * H_ * HD_ * SP_ * sizeof(__half), 0);

    im2col_kernel<<<(Mp * W_ + 255) / 256, 256>>>(x, i2c);
    convw_h_kernel<<<(W_ * W_ + 255) / 256, 256>>>(conv_w, convw16);
    // qkv concat transpose: out layer stride QKV_*W_, row offsets 0/768/1536
    transpose_h_kernel<<<dim3(W_/32, W_/32, L_), blkT>>>(wq, wqkvT, W_, W_, (long long)QKV_*W_, 0);
    transpose_h_kernel<<<dim3(W_/32, W_/32, L_), blkT>>>(wk, wqkvT, W_, W_, (long long)QKV_*W_, W_);
    transpose_h_kernel<<<dim3(W_/32, W_/32, L_), blkT>>>(wv, wqkvT, W_, W_, (long long)QKV_*W_, 2*W_);
    bias_concat_kernel<<<(L_*QKV_ + 255) / 256, 256>>>(bq, bk, bv, bqkv);
    transpose_h_kernel<<<dim3(W_/32,  W_/32,  L_), blkT>>>(wo, woT, W_, W_, (long long)W_*W_, 0);
    transpose_h_kernel<<<dim3(FF_/32, W_/32,  L_), blkT>>>(w1, w1T, W_, FF_, (long long)W_*FF_, 0);
    transpose_h_kernel<<<dim3(W_/32,  FF_/32, L_), blkT>>>(w2, w2T, FF_, W_, (long long)FF_*W_, 0);
    transpose_h_kernel<<<dim3(E_/32,  W_/32,  1),  blkT>>>(proj, projT, W_, E_, (long long)W_*E_, 0);

    {   // patch embed GEMM -> tok (f32)
        dim3 grid(3, (Mp + 127) / 128, 1);
        gemm_wide<1,0,0,0><<<grid, 512, WSMEM>>>(i2c, convw16, conv_b, tok,
            nullptr, nullptr, nullptr, Mp, W_, W_, W_, W_, W_, 0,0,0,0,0,0);
    }
    assemble_kernel<<<(BSW_ + 255) / 256, 256>>>(tok, cls_tok, pe, h);

    const int nrows_att = B_ * H_ * S_;
    dim3 gridQKV(QKV_ / 256, (M + 127) / 128, 1);   // (9, 50)
    dim3 gridW  (3, (M + 127) / 128, 1);            // (3, 50)
    dim3 gridFF (FF_ / 256, (M + 127) / 128, 1);    // (12, 50)
    dim3 gridSc (1, 2, B_ * H_);
    dim3 gridAv (1, 2, B_ * H_);

    const long long qBs  = (long long)S_ * W_;
    const long long aZb  = (long long)H_ * S_ * ALD_, aZh = (long long)S_ * ALD_;
    const long long ahZb = (long long)H_ * S_ * SP_,  ahZh = (long long)S_ * SP_;
    const long long vZb  = (long long)H_ * HD_ * SP_, vZh = (long long)HD_ * SP_;
    const long long oBs  = (long long)S_ * W_;

    for (int l = 0; l < L_; l++) {
        const size_t bOff = (size_t)l * W_;

        layernorm_kernel<<<M, 256>>>(h, ln1_g + bOff, ln1_b + bOff, y);
        // fused QKV: q->qh, k->kh, v->vT
        gemm_wide<1,0,0,3><<<gridQKV, 512, WSMEM>>>(y, wqkvT + (size_t)l * QKV_ * W_,
            bqkv + (size_t)l * QKV_, nullptr, qh, kh, vT,
            M, QKV_, W_, W_, W_, 0, 0,0,0,0,0,0);
        // scores
        gemm_wide<0,0,0,0><<<gridSc, 512, WSMEM>>>(qh, kh, nullptr, att,
            nullptr, nullptr, nullptr, S_, S_, HD_, W_, W_, ALD_,
            qBs, (long long)HD_, qBs, (long long)HD_, aZb, aZh);
        softmax_kernel<<<(nrows_att + 3) / 4, 128>>>(att, atth, nrows_att);
        // AV
        gemm_av<<<gridAv, 256, GEMM_SMEM>>>(atth, vT, o,
            S_, HD_, SP_, SP_, SP_, W_,
            ahZb, ahZh, vZb, vZh, oBs, (long long)HD_);
        // O-proj (+residual)
        gemm_wide<1,1,0,0><<<gridW, 512, WSMEM>>>(o, woT + (size_t)l * W_ * W_,
            bo + bOff, h, nullptr, nullptr, nullptr,
            M, W_, W_, W_, W_, W_, 0,0,0,0,0,0);
        layernorm_kernel<<<M, 256>>>(h, ln2_g + bOff, ln2_b + bOff, y);
        // FF1 (+gelu, f16 out)
        gemm_wide<1,0,1,1><<<gridFF, 512, WSMEM>>>(y, w1T + (size_t)l * W_ * FF_,
            b1 + (size_t)l * FF_, nullptr, ff, nullptr, nullptr,
            M, FF_, W_, W_, W_, FF_, 0,0,0,0,0,0);
        // FF2 (+residual)
        gemm_wide<1,1,0,0><<<gridW, 512, WSMEM>>>(ff, w2T + (size_t)l * FF_ * W_,
            b2 + bOff, h, nullptr, nullptr, nullptr,
            M, W_, FF_, FF_, FF_, W_, 0,0,0,0,0,0);
    }

    gather_cls_kernel<<<(B_ * W_ + 255) / 256, 256>>>(h, cls);
    {
        dim3 grid(2, 1, 1);
        gemm_wide<0,0,0,0><<<grid, 512, WSMEM>>>(cls, projT, nullptr, out,
            nullptr, nullptr, nullptr, B_, E_, W_, W_, W_, E_, 0,0,0,0,0,0);
    }
    l2norm_kernel<<<B_, 256>>>(out);
}

// round 9
// speedup vs baseline: 3.0896x; 1.1502x over previous
#include <cuda_runtime.h>
#include <cuda_fp16.h>
#include <math.h>
#include <stdint.h>

// ---------------- problem constants ----------------
#define B_  32
#define C_  3
#define IMG_ 224
#define P_  16
#define W_  768
#define L_  12
#define H_  12
#define S_  197
#define HD_ 64
#define FF_ 3072
#define E_  512
#define NPATCH_ 196
#define BSW_ (B_*S_*W_)
#define SKP_ 224           // padded kv length
#define QKV_ 2304

// ---------------- scratch ----------------
__device__ float  g_h   [BSW_];
__device__ __half g_y   [BSW_];
__device__ __half g_qh  [BSW_];
__device__ __half g_kh  [BSW_];
__device__ __half g_vh  [BSW_];
__device__ __half g_o   [BSW_];
__device__ __half g_ff  [B_*S_*FF_];
__device__ __half g_im2col[B_*NPATCH_*W_];
__device__ float  g_tok [B_*NPATCH_*W_];
__device__ __half g_cls [B_*W_];
__device__ __half g_convw16[W_*W_];
__device__ __half g_wqkvT[L_*QKV_*W_];
__device__ float  g_bqkv [L_*QKV_];
__device__ __half g_woT [L_*W_*W_];
__device__ __half g_w1T [L_*W_*FF_];
__device__ __half g_w2T [L_*FF_*W_];
__device__ __half g_projT[W_*E_];

__device__ __forceinline__ float gelu_exact(float v) {
    return 0.5f * v * (1.0f + erff(v * 0.70710678118654752f));
}
__device__ __forceinline__ uint32_t smem_u32(const void* p) {
    uint32_t a;
    asm("{ .reg .u64 t; cvta.to.shared.u64 t, %1; cvt.u32.u64 %0, t; }" : "=r"(a) : "l"(p));
    return a;
}

#define LDSM_X4(r, addr) \
    asm volatile("ldmatrix.sync.aligned.m8n8.x4.shared.b16 {%0,%1,%2,%3}, [%4];" \
        : "=r"((r)[0]), "=r"((r)[1]), "=r"((r)[2]), "=r"((r)[3]) : "r"(addr))
#define LDSM_X2(r, addr) \
    asm volatile("ldmatrix.sync.aligned.m8n8.x2.shared.b16 {%0,%1}, [%2];" \
        : "=r"((r)[0]), "=r"((r)[1]) : "r"(addr))
#define LDSM_X2T(r, addr) \
    asm volatile("ldmatrix.sync.aligned.m8n8.x2.trans.shared.b16 {%0,%1}, [%2];" \
        : "=r"((r)[0]), "=r"((r)[1]) : "r"(addr))

__device__ __forceinline__ void cp16(uint32_t dst, const void* src, bool valid) {
    int sz = valid ? 16 : 0;
    asm volatile("cp.async.cg.shared.global [%0], [%1], 16, %2;"
                 :: "r"(dst), "l"(src), "r"(sz));
}
#define CP_COMMIT() asm volatile("cp.async.commit_group;" ::: "memory")
#define CP_WAIT2()  asm volatile("cp.async.wait_group 2;" ::: "memory")
#define CP_WAIT0()  asm volatile("cp.async.wait_group 0;" ::: "memory")

#define MMA16816(acc, af, bf) \
    asm volatile("mma.sync.aligned.m16n8k16.row.col.f32.f16.f16.f32 " \
        "{%0,%1,%2,%3}, {%4,%5,%6,%7}, {%8,%9}, {%0,%1,%2,%3};" \
        : "+f"((acc)[0]), "+f"((acc)[1]), "+f"((acc)[2]), "+f"((acc)[3]) \
        : "r"((af)[0]), "r"((af)[1]), "r"((af)[2]), "r"((af)[3]), \
          "r"((bf)[0]), "r"((bf)[1]))

// =====================================================================
// WIDE GEMM: 128x256 CTA tile, 512 threads, KT=32, 4-stage cp.async.
// OUT_MODE: 0 = f32 C (opt ACCUM/bias), 1 = f16 Ch (opt gelu), 3 = QKV route.
// =====================================================================
#define WSTRIDE 80
#define ASTG (128 * WSTRIDE)
#define BSTG (256 * WSTRIDE)
#define WSMEM (4 * (ASTG + BSTG))         // 122880

template<int HAS_BIAS, int ACCUM, int DO_GELU, int OUT_MODE>
__global__ __launch_bounds__(512)
void gemm_wide(const __half* __restrict__ A, const __half* __restrict__ Bt,
               const float* __restrict__ bias, float* __restrict__ C,
               __half* __restrict__ Ch, __half* __restrict__ Kh,
               __half* __restrict__ Vh,
               int M, int N, int K, int lda, int ldb, int ldc)
{
    extern __shared__ __align__(128) uint8_t sm[];
    uint8_t* smA = sm;
    uint8_t* smB = sm + 4 * ASTG;

    const int t    = threadIdx.x;
    const int warp = t >> 5, lane = t & 31;
    const int m0   = blockIdx.y * 128;
    const int n0   = blockIdx.x * 256;
    const int wm   = (warp >> 3) * 64;
    const int wn   = (warp & 7) * 32;
    const int grp  = lane >> 2;
    const int idx  = lane & 3;

    float acc[4][4][4];
    #pragma unroll
    for (int a = 0; a < 4; a++)
        #pragma unroll
        for (int b = 0; b < 4; b++)
            #pragma unroll
            for (int c = 0; c < 4; c++) acc[a][b][c] = 0.0f;

    const uint32_t saA = smem_u32(smA);
    const uint32_t saB = smem_u32(smB);

    const int rowX = t >> 2;
    const int ck   = t & 3;
    const bool aValid  = (m0 + rowX) < M;
    const bool bValid0 = (n0 + rowX) < N;
    const bool bValid1 = (n0 + rowX + 128) < N;
    const __half* aBase  = A  + (size_t)(m0 + rowX) * lda + ck * 8;
    const __half* bBase0 = Bt + (size_t)(n0 + rowX) * ldb + ck * 8;
    const __half* bBase1 = Bt + (size_t)(n0 + rowX + 128) * ldb + ck * 8;
    const uint32_t dA  = saA + rowX * WSTRIDE + ck * 16;
    const uint32_t dB0 = saB + rowX * WSTRIDE + ck * 16;
    const uint32_t dB1 = saB + (rowX + 128) * WSTRIDE + ck * 16;

    const int nk = K / 32;

    auto load_stage = [&](int kt, int buf) {
        const bool ok = kt < nk;
        const int ko = ok ? kt * 32 : 0;
        cp16(dA  + buf * ASTG, aBase  + ko, ok && aValid);
        cp16(dB0 + buf * BSTG, bBase0 + ko, ok && bValid0);
        cp16(dB1 + buf * BSTG, bBase1 + ko, ok && bValid1);
    };

    const int aoff = (wm + (lane & 15)) * WSTRIDE + (lane >> 4) * 16;
    const int boff = (wn + (lane & 7))  * WSTRIDE + ((lane >> 3) & 1) * 16;

    auto compute = [&](int buf) {
        const uint32_t sa = saA + buf * ASTG;
        const uint32_t sb = saB + buf * BSTG;
        #pragma unroll
        for (int ks = 0; ks < 2; ks++) {
            uint32_t af[4][4], bf[4][2];
            #pragma unroll
            for (int mt = 0; mt < 4; mt++)
                LDSM_X4(af[mt], sa + aoff + mt * 16 * WSTRIDE + ks * 32);
            #pragma unroll
            for (int nt = 0; nt < 4; nt++)
                LDSM_X2(bf[nt], sb + boff + nt * 8 * WSTRIDE + ks * 32);
            #pragma unroll
            for (int mt = 0; mt < 4; mt++)
                #pragma unroll
                for (int nt = 0; nt < 4; nt++)
                    MMA16816(acc[mt][nt], af[mt], bf[nt]);
        }
    };

    #pragma unroll
    for (int s = 0; s < 3; s++) {
        load_stage(s, s);
        CP_COMMIT();
    }

    for (int kt = 0; kt < nk; kt++) {
        CP_WAIT2();
        __syncthreads();
        load_stage(kt + 3, (kt + 3) & 3);
        CP_COMMIT();
        compute(kt & 3);
    }

    #pragma unroll
    for (int mt = 0; mt < 4; mt++) {
        const int r0 = m0 + wm + mt * 16 + grp;
        #pragma unroll
        for (int half = 0; half < 2; half++) {
            const int gm = r0 + half * 8;
            if (gm >= M) continue;
            #pragma unroll
            for (int nt = 0; nt < 4; nt++) {
                const int gn = n0 + wn + nt * 8 + idx * 2;
                if (gn >= N) continue;
                float v0 = acc[mt][nt][half * 2 + 0];
                float v1 = acc[mt][nt][half * 2 + 1];
                if (HAS_BIAS) { v0 += bias[gn]; v1 += bias[gn + 1]; }
                if (DO_GELU)  { v0 = gelu_exact(v0); v1 = gelu_exact(v1); }
                if (OUT_MODE == 3) {
                    __half2 hv = __floats2half2_rn(v0, v1);
                    if (gn < W_)
                        *reinterpret_cast<__half2*>(Ch + (size_t)gm * W_ + gn) = hv;
                    else if (gn < 2 * W_)
                        *reinterpret_cast<__half2*>(Kh + (size_t)gm * W_ + gn - W_) = hv;
                    else
                        *reinterpret_cast<__half2*>(Vh + (size_t)gm * W_ + gn - 2 * W_) = hv;
                } else if (OUT_MODE == 1) {
                    *reinterpret_cast<__half2*>(Ch + (size_t)gm * ldc + gn) =
                        __floats2half2_rn(v0, v1);
                } else {
                    float* p = C + (size_t)gm * ldc + gn;
                    if (ACCUM) {
                        float2 old = *reinterpret_cast<float2*>(p);
                        v0 += old.x; v1 += old.y;
                    }
                    *reinterpret_cast<float2*>(p) = make_float2(v0, v1);
                }
            }
        }
    }
}

// =====================================================================
// FUSED ATTENTION: per CTA = one (b,h), one 128-row q tile.
// scores (HMMA) -> softmax (regs + smem reduce) -> probs smem f16 -> AV (HMMA).
// =====================================================================
#define KSTR 144                         // 128B data + 16 pad (q,k,v rows)
#define PSTR 464                         // 448B data + 16 pad (probs rows)
#define SM_Q 0
#define SM_K (SM_Q + 128 * KSTR)         // 18432
#define SM_V (SM_K + SKP_ * KSTR)        // 50688
#define SM_P (SM_V + SKP_ * KSTR)        // 82944
#define ATT_SMEM (SM_P + 128 * PSTR)     // 142336

__global__ __launch_bounds__(256)
void attn_fused(const __half* __restrict__ qh, const __half* __restrict__ kh,
                const __half* __restrict__ vh, __half* __restrict__ o)
{
    extern __shared__ __align__(128) uint8_t sm[];
    __shared__ float red[128][4];

    const int z  = blockIdx.y;
    const int b  = z / H_, h = z % H_;
    const int m0 = blockIdx.x * 128;

    const int t    = threadIdx.x;
    const int warp = t >> 5, lane = t & 31;
    const int wm   = (warp >> 2) * 64;    // 0 or 64
    const int wn   = (warp & 3) * 56;     // scores N partition (224/4)
    const int wnv  = (warp & 3) * 16;     // AV N partition (64/4)
    const int grp  = lane >> 2;
    const int idx  = lane & 3;
    const int wc   = warp & 3;            // warp column id

    const uint32_t sq = smem_u32(sm) + SM_Q;
    const uint32_t sk = smem_u32(sm) + SM_K;
    const uint32_t sv = smem_u32(sm) + SM_V;
    const uint32_t sp = smem_u32(sm) + SM_P;

    const __half* qbase = qh + ((size_t)b * S_) * W_ + h * HD_;
    const __half* kbase = kh + ((size_t)b * S_) * W_ + h * HD_;
    const __half* vbase = vh + ((size_t)b * S_) * W_ + h * HD_;

    // ---- load q (128 rows x 128B) ----
    #pragma unroll
    for (int i = 0; i < 4; i++) {
        const int c = t + i * 256;        // 0..1023
        const int r = c >> 3, ck = c & 7;
        cp16(sq + r * KSTR + ck * 16, qbase + (size_t)(m0 + r) * W_ + ck * 8,
             (m0 + r) < S_);
    }
    // ---- load k, v (224 rows x 128B, zfill pad) ----
    #pragma unroll
    for (int i = 0; i < 7; i++) {
        const int c = t + i * 256;        // 0..1791
        const int r = c >> 3, ck = c & 7;
        cp16(sk + r * KSTR + ck * 16, kbase + (size_t)r * W_ + ck * 8, r < S_);
        cp16(sv + r * KSTR + ck * 16, vbase + (size_t)r * W_ + ck * 8, r < S_);
    }
    CP_COMMIT();
    CP_WAIT0();
    __syncthreads();

    // ---- phase 1: scores = q @ k^T (M=128, N=224, K=64) ----
    float acc[4][7][4];
    #pragma unroll
    for (int a = 0; a < 4; a++)
        #pragma unroll
        for (int n = 0; n < 7; n++)
            #pragma unroll
            for (int c = 0; c < 4; c++) acc[a][n][c] = 0.0f;

    const int aoffq = (wm + (lane & 15)) * KSTR + (lane >> 4) * 16;
    const int boffk = ((lane & 7)) * KSTR + ((lane >> 3) & 1) * 16;

    #pragma unroll
    for (int ks = 0; ks < 4; ks++) {
        uint32_t af[4][4], bf[7][2];
        #pragma unroll
        for (int mt = 0; mt < 4; mt++)
            LDSM_X4(af[mt], sq + aoffq + mt * 16 * KSTR + ks * 32);
        #pragma unroll
        for (int nt = 0; nt < 7; nt++)
            LDSM_X2(bf[nt], sk + boffk + (wn + nt * 8) * KSTR + ks * 32);
        #pragma unroll
        for (int mt = 0; mt < 4; mt++)
            #pragma unroll
            for (int nt = 0; nt < 7; nt++)
                MMA16816(acc[mt][nt], af[mt], bf[nt]);
    }

    // ---- phase 2: softmax (scale 1/8, mask col>=197) ----
    #pragma unroll
    for (int mt = 0; mt < 4; mt++)
        #pragma unroll
        for (int nt = 0; nt < 7; nt++)
            #pragma unroll
            for (int c = 0; c < 4; c++) {
                const int col = wn + nt * 8 + idx * 2 + (c & 1);
                acc[mt][nt][c] = (col < S_) ? acc[mt][nt][c] * 0.125f : -1e30f;
            }

    float gmax[4][2], gsum[4][2];

    // row max
    #pragma unroll
    for (int mt = 0; mt < 4; mt++)
        #pragma unroll
        for (int hf = 0; hf < 2; hf++) {
            float m = -1e30f;
            #pragma unroll
            for (int nt = 0; nt < 7; nt++) {
                m = fmaxf(m, acc[mt][nt][hf * 2 + 0]);
                m = fmaxf(m, acc[mt][nt][hf * 2 + 1]);
            }
            m = fmaxf(m, __shfl_xor_sync(0xffffffffu, m, 1));
            m = fmaxf(m, __shfl_xor_sync(0xffffffffu, m, 2));
            if (idx == 0) red[wm + mt * 16 + hf * 8 + grp][wc] = m;
        }
    __syncthreads();
    #pragma unroll
    for (int mt = 0; mt < 4; mt++)
        #pragma unroll
        for (int hf = 0; hf < 2; hf++) {
            const int row = wm + mt * 16 + hf * 8 + grp;
            gmax[mt][hf] = fmaxf(fmaxf(red[row][0], red[row][1]),
                                 fmaxf(red[row][2], red[row][3]));
        }
    __syncthreads();

    // exp + row sum
    #pragma unroll
    for (int mt = 0; mt < 4; mt++)
        #pragma unroll
        for (int hf = 0; hf < 2; hf++) {
            float s = 0.f;
            #pragma unroll
            for (int nt = 0; nt < 7; nt++) {
                float e0 = expf(acc[mt][nt][hf * 2 + 0] - gmax[mt][hf]);
                float e1 = expf(acc[mt][nt][hf * 2 + 1] - gmax[mt][hf]);
                acc[mt][nt][hf * 2 + 0] = e0;
                acc[mt][nt][hf * 2 + 1] = e1;
                s += e0 + e1;
            }
            s += __shfl_xor_sync(0xffffffffu, s, 1);
            s += __shfl_xor_sync(0xffffffffu, s, 2);
            if (idx == 0) red[wm + mt * 16 + hf * 8 + grp][wc] = s;
        }
    __syncthreads();
    #pragma unroll
    for (int mt = 0; mt < 4; mt++)
        #pragma unroll
        for (int hf = 0; hf < 2; hf++) {
            const int row = wm + mt * 16 + hf * 8 + grp;
            gsum[mt][hf] = red[row][0] + red[row][1] + red[row][2] + red[row][3];
        }

    // probs -> smem fp16
    #pragma unroll
    for (int mt = 0; mt < 4; mt++)
        #pragma unroll
        for (int hf = 0; hf < 2; hf++) {
            const int row = wm + mt * 16 + hf * 8 + grp;
            const float inv = 1.0f / gsum[mt][hf];
            #pragma unroll
            for (int nt = 0; nt < 7; nt++) {
                const int col = wn + nt * 8 + idx * 2;
                *reinterpret_cast<__half2*>(reinterpret_cast<uint8_t*>(sm) + SM_P +
                                            row * PSTR + col * 2) =
                    __floats2half2_rn(acc[mt][nt][hf * 2 + 0] * inv,
                                      acc[mt][nt][hf * 2 + 1] * inv);
            }
        }
    __syncthreads();

    // ---- phase 3: out = probs @ v (M=128, N=64, K=224) ----
    float acc2[4][2][4];
    #pragma unroll
    for (int a = 0; a < 4; a++)
        #pragma unroll
        for (int n = 0; n < 2; n++)
            #pragma unroll
            for (int c = 0; c < 4; c++) acc2[a][n][c] = 0.0f;

    const int aoffp = (wm + (lane & 15)) * PSTR + (lane >> 4) * 16;

    #pragma unroll
    for (int ks = 0; ks < 14; ks++) {
        uint32_t af[4][4], bf[2][2];
        #pragma unroll
        for (int mt = 0; mt < 4; mt++)
            LDSM_X4(af[mt], sp + aoffp + mt * 16 * PSTR + ks * 32);
        #pragma unroll
        for (int nt = 0; nt < 2; nt++)
            LDSM_X2T(bf[nt], sv + (ks * 16 + (lane & 7) + ((lane >> 3) & 1) * 8) * KSTR
                              + (wnv + nt * 8) * 2);
        #pragma unroll
        for (int mt = 0; mt < 4; mt++)
            #pragma unroll
            for (int nt = 0; nt < 2; nt++)
                MMA16816(acc2[mt][nt], af[mt], bf[nt]);
    }

    // ---- epilogue -> o[b, s, h*64+d] ----
    __half* obase = o + ((size_t)b * S_) * W_ + h * HD_;
    #pragma unroll
    for (int mt = 0; mt < 4; mt++)
        #pragma unroll
        for (int hf = 0; hf < 2; hf++) {
            const int gs = m0 + wm + mt * 16 + hf * 8 + grp;
            if (gs >= S_) continue;
            #pragma unroll
            for (int nt = 0; nt < 2; nt++) {
                const int d = wnv + nt * 8 + idx * 2;
                *reinterpret_cast<__half2*>(obase + (size_t)gs * W_ + d) =
                    __floats2half2_rn(acc2[mt][nt][hf * 2 + 0],
                                      acc2[mt][nt][hf * 2 + 1]);
            }
        }
}

// ---------------- transpose f32->f16, strided/offset output ----------------
__global__ void transpose_h_kernel(const float* __restrict__ in, __half* __restrict__ out,
                                   int R, int Cc, long long ldOut, int rowOff)
{
    __shared__ float tile[32][33];
    const size_t li = (size_t)blockIdx.z * R * Cc;
    const int c0 = blockIdx.x * 32, r0 = blockIdx.y * 32;
    const int x = threadIdx.x, y = threadIdx.y;
    #pragma unroll
    for (int j = 0; j < 32; j += 8)
        tile[y + j][x] = in[li + (size_t)(r0 + y + j) * Cc + c0 + x];
    __syncthreads();
    #pragma unroll
    for (int j = 0; j < 32; j += 8)
        out[(size_t)blockIdx.z * ldOut + (size_t)(rowOff + c0 + y + j) * R + r0 + x] =
            __float2half(tile[x][y + j]);
}

__global__ void convw_h_kernel(const float* __restrict__ in, __half* __restrict__ out)
{
    int i = blockIdx.x * 256 + threadIdx.x;
    if (i < W_ * W_) out[i] = __float2half(in[i]);
}

__global__ void bias_concat_kernel(const float* __restrict__ bq, const float* __restrict__ bk,
                                   const float* __restrict__ bv, float* __restrict__ o)
{
    int i = blockIdx.x * 256 + threadIdx.x;
    if (i >= L_ * QKV_) return;
    const int l = i / QKV_, j = i % QKV_;
    float v = (j < W_) ? bq[l * W_ + j]
            : (j < 2 * W_) ? bk[l * W_ + j - W_]
            : bv[l * W_ + j - 2 * W_];
    o[i] = v;
}

// ---------------- im2col (fp16) ----------------
__global__ void im2col_kernel(const float* __restrict__ x, __half* __restrict__ out)
{
    const int total = B_ * NPATCH_ * W_;
    int idx = blockIdx.x * 256 + threadIdx.x;
    if (idx >= total) return;
    const int kk = idx % W_;
    const int r  = idx / W_;
    const int b  = r / NPATCH_;
    const int p  = r % NPATCH_;
    const int ph = p / 14, pw = p % 14;
    const int c  = kk >> 8;
    const int py = (kk >> 4) & 15;
    const int px = kk & 15;
    out[idx] = __float2half(
        x[(((size_t)b * C_ + c) * IMG_ + ph * P_ + py) * IMG_ + pw * P_ + px]);
}

// ---------------- assemble ----------------
__global__ void assemble_kernel(const float* __restrict__ tok,
                                const float* __restrict__ cls,
                                const float* __restrict__ pe,
                                float* __restrict__ h)
{
    int idx = blockIdx.x * 256 + threadIdx.x;
    if (idx >= BSW_) return;
    const int w  = idx % W_;
    const int bs = idx / W_;
    const int s  = bs % S_;
    const int b  = bs / S_;
    float v = (s == 0) ? cls[w] : tok[((size_t)b * NPATCH_ + (s - 1)) * W_ + w];
    h[idx] = v + pe[(size_t)s * W_ + w];
}

// ---------------- layernorm ----------------
__global__ void layernorm_kernel(const float* __restrict__ x,
                                 const float* __restrict__ gamma,
                                 const float* __restrict__ beta,
                                 __half* __restrict__ y)
{
    const int row = blockIdx.x;
    const float* xr = x + (size_t)row * W_;
    float s = 0.f, s2 = 0.f;
    for (int i = threadIdx.x; i < W_; i += 256) {
        float v = xr[i];
        s += v; s2 += v * v;
    }
    for (int off = 16; off > 0; off >>= 1) {
        s  += __shfl_down_sync(0xffffffffu, s, off);
        s2 += __shfl_down_sync(0xffffffffu, s2, off);
    }
    __shared__ float rs[8], rs2[8];
    const int warp = threadIdx.x >> 5, lane = threadIdx.x & 31;
    if (lane == 0) { rs[warp] = s; rs2[warp] = s2; }
    __syncthreads();
    __shared__ float mean_sh, inv_sh;
    if (threadIdx.x == 0) {
        float ts = 0.f, ts2 = 0.f;
        for (int i = 0; i < 8; i++) { ts += rs[i]; ts2 += rs2[i]; }
        float mean = ts * (1.0f / W_);
        float var  = ts2 * (1.0f / W_) - mean * mean;
        mean_sh = mean;
        inv_sh  = rsqrtf(var + 1e-5f);
    }
    __syncthreads();
    const float mean = mean_sh, inv = inv_sh;
    __half* yr = y + (size_t)row * W_;
    for (int i = threadIdx.x; i < W_; i += 256)
        yr[i] = __float2half((xr[i] - mean) * inv * gamma[i] + beta[i]);
}

// ---------------- gather / l2norm ----------------
__global__ void gather_cls_kernel(const float* __restrict__ h, __half* __restrict__ cls)
{
    int idx = blockIdx.x * 256 + threadIdx.x;
    if (idx >= B_ * W_) return;
    const int b = idx / W_, w = idx % W_;
    cls[idx] = __float2half(h[(size_t)b * S_ * W_ + w]);
}

__global__ void l2norm_kernel(float* __restrict__ out)
{
    const int row = blockIdx.x;
    float* r = out + (size_t)row * E_;
    float s = 0.f;
    for (int i = threadIdx.x; i < E_; i += 256) { float v = r[i]; s += v * v; }
    for (int off = 16; off > 0; off >>= 1) s += __shfl_down_sync(0xffffffffu, s, off);
    __shared__ float rs[8];
    const int warp = threadIdx.x >> 5, lane = threadIdx.x & 31;
    if (lane == 0) rs[warp] = s;
    __syncthreads();
    __shared__ float inv_sh;
    if (threadIdx.x == 0) {
        float ts = 0.f;
        for (int i = 0; i < 8; i++) ts += rs[i];
        inv_sh = rsqrtf(ts);
    }
    __syncthreads();
    const float inv = inv_sh;
    for (int i = threadIdx.x; i < E_; i += 256) r[i] *= inv;
}

// ---------------- launch ----------------
extern "C" void kernel_launch(void* const* d_in, const int* in_sizes, int n_in,
                              void* d_out, int out_size)
{
    (void)in_sizes; (void)n_in; (void)out_size;

    const float* x       = (const float*)d_in[0];
    const float* conv_w  = (const float*)d_in[1];
    const float* conv_b  = (const float*)d_in[2];
    const float* cls_tok = (const float*)d_in[3];
    const float* pe      = (const float*)d_in[4];
    const float* ln1_g   = (const float*)d_in[5];
    const float* ln1_b   = (const float*)d_in[6];
    const float* wq      = (const float*)d_in[7];
    const float* bq      = (const float*)d_in[8];
    const float* wk      = (const float*)d_in[9];
    const float* bk      = (const float*)d_in[10];
    const float* wv      = (const float*)d_in[11];
    const float* bv      = (const float*)d_in[12];
    const float* wo      = (const float*)d_in[13];
    const float* bo      = (const float*)d_in[14];
    const float* ln2_g   = (const float*)d_in[15];
    const float* ln2_b   = (const float*)d_in[16];
    const float* w1      = (const float*)d_in[17];
    const float* b1      = (const float*)d_in[18];
    const float* w2      = (const float*)d_in[19];
    const float* b2      = (const float*)d_in[20];
    const float* proj    = (const float*)d_in[21];
    float* out           = (float*)d_out;

    float  *h, *tok, *bqkv;
    __half *y, *qh, *kh, *vh, *o, *ff, *i2c, *cls, *convw16;
    __half *wqkvT, *woT, *w1T, *w2T, *projT;
    cudaGetSymbolAddress((void**)&h,    g_h);
    cudaGetSymbolAddress((void**)&y,    g_y);
    cudaGetSymbolAddress((void**)&qh,   g_qh);
    cudaGetSymbolAddress((void**)&kh,   g_kh);
    cudaGetSymbolAddress((void**)&vh,   g_vh);
    cudaGetSymbolAddress((void**)&o,    g_o);
    cudaGetSymbolAddress((void**)&ff,   g_ff);
    cudaGetSymbolAddress((void**)&i2c,  g_im2col);
    cudaGetSymbolAddress((void**)&tok,  g_tok);
    cudaGetSymbolAddress((void**)&cls,  g_cls);
    cudaGetSymbolAddress((void**)&convw16, g_convw16);
    cudaGetSymbolAddress((void**)&wqkvT, g_wqkvT);
    cudaGetSymbolAddress((void**)&bqkv,  g_bqkv);
    cudaGetSymbolAddress((void**)&woT,  g_woT);
    cudaGetSymbolAddress((void**)&w1T,  g_w1T);
    cudaGetSymbolAddress((void**)&w2T,  g_w2T);
    cudaGetSymbolAddress((void**)&projT, g_projT);

    cudaFuncSetAttribute(gemm_wide<1,0,0,0>, cudaFuncAttributeMaxDynamicSharedMemorySize, WSMEM);
    cudaFuncSetAttribute(gemm_wide<1,0,0,3>, cudaFuncAttributeMaxDynamicSharedMemorySize, WSMEM);
    cudaFuncSetAttribute(gemm_wide<0,0,0,0>, cudaFuncAttributeMaxDynamicSharedMemorySize, WSMEM);
    cudaFuncSetAttribute(gemm_wide<1,1,0,0>, cudaFuncAttributeMaxDynamicSharedMemorySize, WSMEM);
    cudaFuncSetAttribute(gemm_wide<1,0,1,1>, cudaFuncAttributeMaxDynamicSharedMemorySize, WSMEM);
    cudaFuncSetAttribute(attn_fused, cudaFuncAttributeMaxDynamicSharedMemorySize, ATT_SMEM);

    const int M  = B_ * S_;       // 6304
    const int Mp = B_ * NPATCH_;  // 6272
    dim3 blkT(32, 8);

    im2col_kernel<<<(Mp * W_ + 255) / 256, 256>>>(x, i2c);
    convw_h_kernel<<<(W_ * W_ + 255) / 256, 256>>>(conv_w, convw16);
    transpose_h_kernel<<<dim3(W_/32, W_/32, L_), blkT>>>(wq, wqkvT, W_, W_, (long long)QKV_*W_, 0);
    transpose_h_kernel<<<dim3(W_/32, W_/32, L_), blkT>>>(wk, wqkvT, W_, W_, (long long)QKV_*W_, W_);
    transpose_h_kernel<<<dim3(W_/32, W_/32, L_), blkT>>>(wv, wqkvT, W_, W_, (long long)QKV_*W_, 2*W_);
    bias_concat_kernel<<<(L_*QKV_ + 255) / 256, 256>>>(bq, bk, bv, bqkv);
    transpose_h_kernel<<<dim3(W_/32,  W_/32,  L_), blkT>>>(wo, woT, W_, W_, (long long)W_*W_, 0);
    transpose_h_kernel<<<dim3(FF_/32, W_/32,  L_), blkT>>>(w1, w1T, W_, FF_, (long long)W_*FF_, 0);
    transpose_h_kernel<<<dim3(W_/32,  FF_/32, L_), blkT>>>(w2, w2T, FF_, W_, (long long)FF_*W_, 0);
    transpose_h_kernel<<<dim3(E_/32,  W_/32,  1),  blkT>>>(proj, projT, W_, E_, (long long)W_*E_, 0);

    {   // patch embed GEMM -> tok (f32)
        dim3 grid(3, (Mp + 127) / 128, 1);
        gemm_wide<1,0,0,0><<<grid, 512, WSMEM>>>(i2c, convw16, conv_b, tok,
            nullptr, nullptr, nullptr, Mp, W_, W_, W_, W_, W_);
    }
    assemble_kernel<<<(BSW_ + 255) / 256, 256>>>(tok, cls_tok, pe, h);

    dim3 gridQKV(QKV_ / 256, (M + 127) / 128, 1);
    dim3 gridW  (3, (M + 127) / 128, 1);
    dim3 gridFF (FF_ / 256, (M + 127) / 128, 1);
    dim3 gridAtt(2, B_ * H_, 1);

    for (int l = 0; l < L_; l++) {
        const size_t bOff = (size_t)l * W_;

        layernorm_kernel<<<M, 256>>>(h, ln1_g + bOff, ln1_b + bOff, y);
        gemm_wide<1,0,0,3><<<gridQKV, 512, WSMEM>>>(y, wqkvT + (size_t)l * QKV_ * W_,
            bqkv + (size_t)l * QKV_, nullptr, qh, kh, vh,
            M, QKV_, W_, W_, W_, 0);
        attn_fused<<<gridAtt, 256, ATT_SMEM>>>(qh, kh, vh, o);
        gemm_wide<1,1,0,0><<<gridW, 512, WSMEM>>>(o, woT + (size_t)l * W_ * W_,
            bo + bOff, h, nullptr, nullptr, nullptr,
            M, W_, W_, W_, W_, W_);
        layernorm_kernel<<<M, 256>>>(h, ln2_g + bOff, ln2_b + bOff, y);
        gemm_wide<1,0,1,1><<<gridFF, 512, WSMEM>>>(y, w1T + (size_t)l * W_ * FF_,
            b1 + (size_t)l * FF_, nullptr, ff, nullptr, nullptr,
            M, FF_, W_, W_, W_, FF_);
        gemm_wide<1,1,0,0><<<gridW, 512, WSMEM>>>(ff, w2T + (size_t)l * FF_ * W_,
            b2 + bOff, h, nullptr, nullptr, nullptr,
            M, W_, FF_, FF_, FF_, W_);
    }

    gather_cls_kernel<<<(B_ * W_ + 255) / 256, 256>>>(h, cls);
    {
        dim3 grid(2, 1, 1);
        gemm_wide<0,0,0,0><<<grid, 512, WSMEM>>>(cls, projT, nullptr, out,
            nullptr, nullptr, nullptr, B_, E_, W_, W_, W_, E_);
    }
    l2norm_kernel<<<B_, 256>>>(out);
}

// round 10
// speedup vs baseline: 3.1287x; 1.0126x over previous
#include <cuda_runtime.h>
#include <cuda_fp16.h>
#include <math.h>
#include <stdint.h>

// ---------------- problem constants ----------------
#define B_  32
#define C_  3
#define IMG_ 224
#define P_  16
#define W_  768
#define L_  12
#define H_  12
#define S_  197
#define HD_ 64
#define FF_ 3072
#define E_  512
#define NPATCH_ 196
#define BSW_ (B_*S_*W_)
#define SKP_ 224
#define QKV_ 2304

// ---------------- scratch ----------------
__device__ float  g_h   [BSW_];
__device__ __half g_y   [BSW_];
__device__ __half g_qh  [BSW_];
__device__ __half g_kh  [BSW_];
__device__ __half g_vh  [BSW_];
__device__ __half g_o   [BSW_];
__device__ __half g_ff  [B_*S_*FF_];
__device__ __half g_im2col[B_*NPATCH_*W_];
__device__ float  g_tok [B_*NPATCH_*W_];
__device__ __half g_cls [B_*W_];
__device__ __half g_convw16[W_*W_];
__device__ __half g_wqkvT[L_*QKV_*W_];
__device__ float  g_bqkv [L_*QKV_];
__device__ __half g_woT [L_*W_*W_];
__device__ __half g_w1T [L_*W_*FF_];
__device__ __half g_w2T [L_*FF_*W_];
__device__ __half g_projT[W_*E_];

__device__ __forceinline__ float gelu_exact(float v) {
    return 0.5f * v * (1.0f + erff(v * 0.70710678118654752f));
}
__device__ __forceinline__ uint32_t smem_u32(const void* p) {
    uint32_t a;
    asm("{ .reg .u64 t; cvta.to.shared.u64 t, %1; cvt.u32.u64 %0, t; }" : "=r"(a) : "l"(p));
    return a;
}

#define LDSM_X4(r, addr) \
    asm volatile("ldmatrix.sync.aligned.m8n8.x4.shared.b16 {%0,%1,%2,%3}, [%4];" \
        : "=r"((r)[0]), "=r"((r)[1]), "=r"((r)[2]), "=r"((r)[3]) : "r"(addr))
#define LDSM_X2(r, addr) \
    asm volatile("ldmatrix.sync.aligned.m8n8.x2.shared.b16 {%0,%1}, [%2];" \
        : "=r"((r)[0]), "=r"((r)[1]) : "r"(addr))
#define LDSM_X2T(r, addr) \
    asm volatile("ldmatrix.sync.aligned.m8n8.x2.trans.shared.b16 {%0,%1}, [%2];" \
        : "=r"((r)[0]), "=r"((r)[1]) : "r"(addr))

__device__ __forceinline__ void cp16(uint32_t dst, const void* src, bool valid) {
    int sz = valid ? 16 : 0;
    asm volatile("cp.async.cg.shared.global [%0], [%1], 16, %2;"
                 :: "r"(dst), "l"(src), "r"(sz));
}
#define CP_COMMIT() asm volatile("cp.async.commit_group;" ::: "memory")
#define CP_WAIT2()  asm volatile("cp.async.wait_group 2;" ::: "memory")
#define CP_WAIT0()  asm volatile("cp.async.wait_group 0;" ::: "memory")

#define MMA16816(acc, af, bf) \
    asm volatile("mma.sync.aligned.m16n8k16.row.col.f32.f16.f16.f32 " \
        "{%0,%1,%2,%3}, {%4,%5,%6,%7}, {%8,%9}, {%0,%1,%2,%3};" \
        : "+f"((acc)[0]), "+f"((acc)[1]), "+f"((acc)[2]), "+f"((acc)[3]) \
        : "r"((af)[0]), "r"((af)[1]), "r"((af)[2]), "r"((af)[3]), \
          "r"((bf)[0]), "r"((bf)[1]))

// =====================================================================
// WIDE GEMM: 128x256 CTA tile, 512 threads, KT=32, 4-stage cp.async.
// OUT_MODE: 0 = f32 C (opt ACCUM/bias), 1 = f16 Ch (opt gelu), 3 = QKV route.
// =====================================================================
#define WSTRIDE 80
#define ASTG (128 * WSTRIDE)
#define BSTG (256 * WSTRIDE)
#define WSMEM (4 * (ASTG + BSTG))         // 122880

template<int HAS_BIAS, int ACCUM, int DO_GELU, int OUT_MODE>
__global__ __launch_bounds__(512)
void gemm_wide(const __half* __restrict__ A, const __half* __restrict__ Bt,
               const float* __restrict__ bias, float* __restrict__ C,
               __half* __restrict__ Ch, __half* __restrict__ Kh,
               __half* __restrict__ Vh,
               int M, int N, int K, int lda, int ldb, int ldc)
{
    extern __shared__ __align__(128) uint8_t sm[];
    uint8_t* smA = sm;
    uint8_t* smB = sm + 4 * ASTG;

    const int t    = threadIdx.x;
    const int warp = t >> 5, lane = t & 31;
    const int m0   = blockIdx.y * 128;
    const int n0   = blockIdx.x * 256;
    const int wm   = (warp >> 3) * 64;
    const int wn   = (warp & 7) * 32;
    const int grp  = lane >> 2;
    const int idx  = lane & 3;

    float acc[4][4][4];
    #pragma unroll
    for (int a = 0; a < 4; a++)
        #pragma unroll
        for (int b = 0; b < 4; b++)
            #pragma unroll
            for (int c = 0; c < 4; c++) acc[a][b][c] = 0.0f;

    const uint32_t saA = smem_u32(smA);
    const uint32_t saB = smem_u32(smB);

    const int rowX = t >> 2;
    const int ck   = t & 3;
    const bool aValid  = (m0 + rowX) < M;
    const bool bValid0 = (n0 + rowX) < N;
    const bool bValid1 = (n0 + rowX + 128) < N;
    const __half* aBase  = A  + (size_t)(m0 + rowX) * lda + ck * 8;
    const __half* bBase0 = Bt + (size_t)(n0 + rowX) * ldb + ck * 8;
    const __half* bBase1 = Bt + (size_t)(n0 + rowX + 128) * ldb + ck * 8;
    const uint32_t dA  = saA + rowX * WSTRIDE + ck * 16;
    const uint32_t dB0 = saB + rowX * WSTRIDE + ck * 16;
    const uint32_t dB1 = saB + (rowX + 128) * WSTRIDE + ck * 16;

    const int nk = K / 32;

    auto load_stage = [&](int kt, int buf) {
        const bool ok = kt < nk;
        const int ko = ok ? kt * 32 : 0;
        cp16(dA  + buf * ASTG, aBase  + ko, ok && aValid);
        cp16(dB0 + buf * BSTG, bBase0 + ko, ok && bValid0);
        cp16(dB1 + buf * BSTG, bBase1 + ko, ok && bValid1);
    };

    const int aoff = (wm + (lane & 15)) * WSTRIDE + (lane >> 4) * 16;
    const int boff = (wn + (lane & 7))  * WSTRIDE + ((lane >> 3) & 1) * 16;

    auto compute = [&](int buf) {
        const uint32_t sa = saA + buf * ASTG;
        const uint32_t sb = saB + buf * BSTG;
        #pragma unroll
        for (int ks = 0; ks < 2; ks++) {
            uint32_t af[4][4], bf[4][2];
            #pragma unroll
            for (int mt = 0; mt < 4; mt++)
                LDSM_X4(af[mt], sa + aoff + mt * 16 * WSTRIDE + ks * 32);
            #pragma unroll
            for (int nt = 0; nt < 4; nt++)
                LDSM_X2(bf[nt], sb + boff + nt * 8 * WSTRIDE + ks * 32);
            #pragma unroll
            for (int mt = 0; mt < 4; mt++)
                #pragma unroll
                for (int nt = 0; nt < 4; nt++)
                    MMA16816(acc[mt][nt], af[mt], bf[nt]);
        }
    };

    #pragma unroll
    for (int s = 0; s < 3; s++) {
        load_stage(s, s);
        CP_COMMIT();
    }

    for (int kt = 0; kt < nk; kt++) {
        CP_WAIT2();
        __syncthreads();
        load_stage(kt + 3, (kt + 3) & 3);
        CP_COMMIT();
        compute(kt & 3);
    }

    #pragma unroll
    for (int mt = 0; mt < 4; mt++) {
        const int r0 = m0 + wm + mt * 16 + grp;
        #pragma unroll
        for (int half = 0; half < 2; half++) {
            const int gm = r0 + half * 8;
            if (gm >= M) continue;
            #pragma unroll
            for (int nt = 0; nt < 4; nt++) {
                const int gn = n0 + wn + nt * 8 + idx * 2;
                if (gn >= N) continue;
                float v0 = acc[mt][nt][half * 2 + 0];
                float v1 = acc[mt][nt][half * 2 + 1];
                if (HAS_BIAS) { v0 += bias[gn]; v1 += bias[gn + 1]; }
                if (DO_GELU)  { v0 = gelu_exact(v0); v1 = gelu_exact(v1); }
                if (OUT_MODE == 3) {
                    __half2 hv = __floats2half2_rn(v0, v1);
                    if (gn < W_)
                        *reinterpret_cast<__half2*>(Ch + (size_t)gm * W_ + gn) = hv;
                    else if (gn < 2 * W_)
                        *reinterpret_cast<__half2*>(Kh + (size_t)gm * W_ + gn - W_) = hv;
                    else
                        *reinterpret_cast<__half2*>(Vh + (size_t)gm * W_ + gn - 2 * W_) = hv;
                } else if (OUT_MODE == 1) {
                    *reinterpret_cast<__half2*>(Ch + (size_t)gm * ldc + gn) =
                        __floats2half2_rn(v0, v1);
                } else {
                    float* p = C + (size_t)gm * ldc + gn;
                    if (ACCUM) {
                        float2 old = *reinterpret_cast<float2*>(p);
                        v0 += old.x; v1 += old.y;
                    }
                    *reinterpret_cast<float2*>(p) = make_float2(v0, v1);
                }
            }
        }
    }
}

// =====================================================================
// NARROW GEMM: 128x128 tile, 256 threads, 2 CTAs/SM (for N=768 GEMMs —
// kills the 1.01-wave->2-wave quantization of the wide kernel).
// f32 out with bias (+residual ACCUM).
// =====================================================================
#define STRIDE 80
#define STAGEB (128 * STRIDE)
#define NSMEM (8 * STAGEB)   // 81920

template<int HAS_BIAS, int ACCUM>
__global__ __launch_bounds__(256, 2)
void gemm_n(const __half* __restrict__ A, const __half* __restrict__ Bt,
            const float* __restrict__ bias, float* __restrict__ C,
            int M, int N, int K, int lda, int ldb, int ldc)
{
    extern __shared__ __align__(128) uint8_t sm[];
    uint8_t* smA = sm;
    uint8_t* smB = sm + 4 * STAGEB;

    const int t    = threadIdx.x;
    const int warp = t >> 5, lane = t & 31;
    const int m0   = blockIdx.y * 128;
    const int n0   = blockIdx.x * 128;
    const int wm   = (warp >> 2) * 64;
    const int wn   = (warp & 3) * 32;
    const int grp  = lane >> 2;
    const int idx  = lane & 3;

    float acc[4][4][4];
    #pragma unroll
    for (int a = 0; a < 4; a++)
        #pragma unroll
        for (int b = 0; b < 4; b++)
            #pragma unroll
            for (int c = 0; c < 4; c++) acc[a][b][c] = 0.0f;

    const uint32_t saA = smem_u32(smA);
    const uint32_t saB = smem_u32(smB);

    const int rowL = t >> 1;
    const int ck0  = (t & 1) * 2;
    const bool aValid = (m0 + rowL) < M;
    const bool bValid = (n0 + rowL) < N;
    const __half* aBase = A + (size_t)(m0 + rowL) * lda + ck0 * 8;
    const __half* bBase = Bt + (size_t)(n0 + rowL) * ldb + ck0 * 8;
    const uint32_t dA = saA + rowL * STRIDE + ck0 * 16;
    const uint32_t dB = saB + rowL * STRIDE + ck0 * 16;

    const int nk = K / 32;

    auto load_stage = [&](int kt, int buf) {
        const bool ok = kt < nk;
        const int ko = ok ? kt * 32 : 0;
        cp16(dA + buf * STAGEB,      aBase + ko,     ok && aValid);
        cp16(dA + buf * STAGEB + 16, aBase + ko + 8, ok && aValid);
        cp16(dB + buf * STAGEB,      bBase + ko,     ok && bValid);
        cp16(dB + buf * STAGEB + 16, bBase + ko + 8, ok && bValid);
    };

    const int aoff = (wm + (lane & 15)) * STRIDE + (lane >> 4) * 16;
    const int boff = (wn + (lane & 7))  * STRIDE + ((lane >> 3) & 1) * 16;

    auto compute = [&](int buf) {
        const uint32_t sa = saA + buf * STAGEB;
        const uint32_t sb = saB + buf * STAGEB;
        #pragma unroll
        for (int ks = 0; ks < 2; ks++) {
            uint32_t af[4][4], bf[4][2];
            #pragma unroll
            for (int mt = 0; mt < 4; mt++)
                LDSM_X4(af[mt], sa + aoff + mt * 16 * STRIDE + ks * 32);
            #pragma unroll
            for (int nt = 0; nt < 4; nt++)
                LDSM_X2(bf[nt], sb + boff + nt * 8 * STRIDE + ks * 32);
            #pragma unroll
            for (int mt = 0; mt < 4; mt++)
                #pragma unroll
                for (int nt = 0; nt < 4; nt++)
                    MMA16816(acc[mt][nt], af[mt], bf[nt]);
        }
    };

    #pragma unroll
    for (int s = 0; s < 3; s++) {
        load_stage(s, s);
        CP_COMMIT();
    }

    for (int kt = 0; kt < nk; kt++) {
        CP_WAIT2();
        __syncthreads();
        load_stage(kt + 3, (kt + 3) & 3);
        CP_COMMIT();
        compute(kt & 3);
    }

    #pragma unroll
    for (int mt = 0; mt < 4; mt++) {
        const int r0 = m0 + wm + mt * 16 + grp;
        #pragma unroll
        for (int half = 0; half < 2; half++) {
            const int gm = r0 + half * 8;
            if (gm >= M) continue;
            #pragma unroll
            for (int nt = 0; nt < 4; nt++) {
                const int gn = n0 + wn + nt * 8 + idx * 2;
                if (gn >= N) continue;
                float v0 = acc[mt][nt][half * 2 + 0];
                float v1 = acc[mt][nt][half * 2 + 1];
                if (HAS_BIAS) { v0 += bias[gn]; v1 += bias[gn + 1]; }
                float* p = C + (size_t)gm * ldc + gn;
                if (ACCUM) {
                    float2 old = *reinterpret_cast<float2*>(p);
                    v0 += old.x; v1 += old.y;
                }
                *reinterpret_cast<float2*>(p) = make_float2(v0, v1);
            }
        }
    }
}

// =====================================================================
// FUSED ATTENTION (round 9, unchanged)
// =====================================================================
#define KSTR 144
#define PSTR 464
#define SM_Q 0
#define SM_K (SM_Q + 128 * KSTR)
#define SM_V (SM_K + SKP_ * KSTR)
#define SM_P (SM_V + SKP_ * KSTR)
#define ATT_SMEM (SM_P + 128 * PSTR)     // 142336

__global__ __launch_bounds__(256)
void attn_fused(const __half* __restrict__ qh, const __half* __restrict__ kh,
                const __half* __restrict__ vh, __half* __restrict__ o)
{
    extern __shared__ __align__(128) uint8_t sm[];
    __shared__ float red[128][4];

    const int z  = blockIdx.y;
    const int b  = z / H_, h = z % H_;
    const int m0 = blockIdx.x * 128;

    const int t    = threadIdx.x;
    const int warp = t >> 5, lane = t & 31;
    const int wm   = (warp >> 2) * 64;
    const int wn   = (warp & 3) * 56;
    const int wnv  = (warp & 3) * 16;
    const int grp  = lane >> 2;
    const int idx  = lane & 3;
    const int wc   = warp & 3;

    const uint32_t sq = smem_u32(sm) + SM_Q;
    const uint32_t sk = smem_u32(sm) + SM_K;
    const uint32_t sv = smem_u32(sm) + SM_V;
    const uint32_t sp = smem_u32(sm) + SM_P;

    const __half* qbase = qh + ((size_t)b * S_) * W_ + h * HD_;
    const __half* kbase = kh + ((size_t)b * S_) * W_ + h * HD_;
    const __half* vbase = vh + ((size_t)b * S_) * W_ + h * HD_;

    #pragma unroll
    for (int i = 0; i < 4; i++) {
        const int c = t + i * 256;
        const int r = c >> 3, ck = c & 7;
        cp16(sq + r * KSTR + ck * 16, qbase + (size_t)(m0 + r) * W_ + ck * 8,
             (m0 + r) < S_);
    }
    #pragma unroll
    for (int i = 0; i < 7; i++) {
        const int c = t + i * 256;
        const int r = c >> 3, ck = c & 7;
        cp16(sk + r * KSTR + ck * 16, kbase + (size_t)r * W_ + ck * 8, r < S_);
        cp16(sv + r * KSTR + ck * 16, vbase + (size_t)r * W_ + ck * 8, r < S_);
    }
    CP_COMMIT();
    CP_WAIT0();
    __syncthreads();

    float acc[4][7][4];
    #pragma unroll
    for (int a = 0; a < 4; a++)
        #pragma unroll
        for (int n = 0; n < 7; n++)
            #pragma unroll
            for (int c = 0; c < 4; c++) acc[a][n][c] = 0.0f;

    const int aoffq = (wm + (lane & 15)) * KSTR + (lane >> 4) * 16;
    const int boffk = ((lane & 7)) * KSTR + ((lane >> 3) & 1) * 16;

    #pragma unroll
    for (int ks = 0; ks < 4; ks++) {
        uint32_t af[4][4], bf[7][2];
        #pragma unroll
        for (int mt = 0; mt < 4; mt++)
            LDSM_X4(af[mt], sq + aoffq + mt * 16 * KSTR + ks * 32);
        #pragma unroll
        for (int nt = 0; nt < 7; nt++)
            LDSM_X2(bf[nt], sk + boffk + (wn + nt * 8) * KSTR + ks * 32);
        #pragma unroll
        for (int mt = 0; mt < 4; mt++)
            #pragma unroll
            for (int nt = 0; nt < 7; nt++)
                MMA16816(acc[mt][nt], af[mt], bf[nt]);
    }

    #pragma unroll
    for (int mt = 0; mt < 4; mt++)
        #pragma unroll
        for (int nt = 0; nt < 7; nt++)
            #pragma unroll
            for (int c = 0; c < 4; c++) {
                const int col = wn + nt * 8 + idx * 2 + (c & 1);
                acc[mt][nt][c] = (col < S_) ? acc[mt][nt][c] * 0.125f : -1e30f;
            }

    float gmax[4][2], gsum[4][2];

    #pragma unroll
    for (int mt = 0; mt < 4; mt++)
        #pragma unroll
        for (int hf = 0; hf < 2; hf++) {
            float m = -1e30f;
            #pragma unroll
            for (int nt = 0; nt < 7; nt++) {
                m = fmaxf(m, acc[mt][nt][hf * 2 + 0]);
                m = fmaxf(m, acc[mt][nt][hf * 2 + 1]);
            }
            m = fmaxf(m, __shfl_xor_sync(0xffffffffu, m, 1));
            m = fmaxf(m, __shfl_xor_sync(0xffffffffu, m, 2));
            if (idx == 0) red[wm + mt * 16 + hf * 8 + grp][wc] = m;
        }
    __syncthreads();
    #pragma unroll
    for (int mt = 0; mt < 4; mt++)
        #pragma unroll
        for (int hf = 0; hf < 2; hf++) {
            const int row = wm + mt * 16 + hf * 8 + grp;
            gmax[mt][hf] = fmaxf(fmaxf(red[row][0], red[row][1]),
                                 fmaxf(red[row][2], red[row][3]));
        }
    __syncthreads();

    #pragma unroll
    for (int mt = 0; mt < 4; mt++)
        #pragma unroll
        for (int hf = 0; hf < 2; hf++) {
            float s = 0.f;
            #pragma unroll
            for (int nt = 0; nt < 7; nt++) {
                float e0 = expf(acc[mt][nt][hf * 2 + 0] - gmax[mt][hf]);
                float e1 = expf(acc[mt][nt][hf * 2 + 1] - gmax[mt][hf]);
                acc[mt][nt][hf * 2 + 0] = e0;
                acc[mt][nt][hf * 2 + 1] = e1;
                s += e0 + e1;
            }
            s += __shfl_xor_sync(0xffffffffu, s, 1);
            s += __shfl_xor_sync(0xffffffffu, s, 2);
            if (idx == 0) red[wm + mt * 16 + hf * 8 + grp][wc] = s;
        }
    __syncthreads();
    #pragma unroll
    for (int mt = 0; mt < 4; mt++)
        #pragma unroll
        for (int hf = 0; hf < 2; hf++) {
            const int row = wm + mt * 16 + hf * 8 + grp;
            gsum[mt][hf] = red[row][0] + red[row][1] + red[row][2] + red[row][3];
        }

    #pragma unroll
    for (int mt = 0; mt < 4; mt++)
        #pragma unroll
        for (int hf = 0; hf < 2; hf++) {
            const int row = wm + mt * 16 + hf * 8 + grp;
            const float inv = 1.0f / gsum[mt][hf];
            #pragma unroll
            for (int nt = 0; nt < 7; nt++) {
                const int col = wn + nt * 8 + idx * 2;
                *reinterpret_cast<__half2*>(reinterpret_cast<uint8_t*>(sm) + SM_P +
                                            row * PSTR + col * 2) =
                    __floats2half2_rn(acc[mt][nt][hf * 2 + 0] * inv,
                                      acc[mt][nt][hf * 2 + 1] * inv);
            }
        }
    __syncthreads();

    float acc2[4][2][4];
    #pragma unroll
    for (int a = 0; a < 4; a++)
        #pragma unroll
        for (int n = 0; n < 2; n++)
            #pragma unroll
            for (int c = 0; c < 4; c++) acc2[a][n][c] = 0.0f;

    const int aoffp = (wm + (lane & 15)) * PSTR + (lane >> 4) * 16;

    #pragma unroll
    for (int ks = 0; ks < 14; ks++) {
        uint32_t af[4][4], bf[2][2];
        #pragma unroll
        for (int mt = 0; mt < 4; mt++)
            LDSM_X4(af[mt], sp + aoffp + mt * 16 * PSTR + ks * 32);
        #pragma unroll
        for (int nt = 0; nt < 2; nt++)
            LDSM_X2T(bf[nt], sv + (ks * 16 + (lane & 7) + ((lane >> 3) & 1) * 8) * KSTR
                              + (wnv + nt * 8) * 2);
        #pragma unroll
        for (int mt = 0; mt < 4; mt++)
            #pragma unroll
            for (int nt = 0; nt < 2; nt++)
                MMA16816(acc2[mt][nt], af[mt], bf[nt]);
    }

    __half* obase = o + ((size_t)b * S_) * W_ + h * HD_;
    #pragma unroll
    for (int mt = 0; mt < 4; mt++)
        #pragma unroll
        for (int hf = 0; hf < 2; hf++) {
            const int gs = m0 + wm + mt * 16 + hf * 8 + grp;
            if (gs >= S_) continue;
            #pragma unroll
            for (int nt = 0; nt < 2; nt++) {
                const int d = wnv + nt * 8 + idx * 2;
                *reinterpret_cast<__half2*>(obase + (size_t)gs * W_ + d) =
                    __floats2half2_rn(acc2[mt][nt][hf * 2 + 0],
                                      acc2[mt][nt][hf * 2 + 1]);
            }
        }
}

// ---------------- transpose f32->f16, strided/offset output ----------------
__global__ void transpose_h_kernel(const float* __restrict__ in, __half* __restrict__ out,
                                   int R, int Cc, long long ldOut, int rowOff)
{
    __shared__ float tile[32][33];
    const size_t li = (size_t)blockIdx.z * R * Cc;
    const int c0 = blockIdx.x * 32, r0 = blockIdx.y * 32;
    const int x = threadIdx.x, y = threadIdx.y;
    #pragma unroll
    for (int j = 0; j < 32; j += 8)
        tile[y + j][x] = in[li + (size_t)(r0 + y + j) * Cc + c0 + x];
    __syncthreads();
    #pragma unroll
    for (int j = 0; j < 32; j += 8)
        out[(size_t)blockIdx.z * ldOut + (size_t)(rowOff + c0 + y + j) * R + r0 + x] =
            __float2half(tile[x][y + j]);
}

__global__ void convw_h_kernel(const float* __restrict__ in, __half* __restrict__ out)
{
    int i = blockIdx.x * 256 + threadIdx.x;
    if (i < W_ * W_) out[i] = __float2half(in[i]);
}

__global__ void bias_concat_kernel(const float* __restrict__ bq, const float* __restrict__ bk,
                                   const float* __restrict__ bv, float* __restrict__ o)
{
    int i = blockIdx.x * 256 + threadIdx.x;
    if (i >= L_ * QKV_) return;
    const int l = i / QKV_, j = i % QKV_;
    float v = (j < W_) ? bq[l * W_ + j]
            : (j < 2 * W_) ? bk[l * W_ + j - W_]
            : bv[l * W_ + j - 2 * W_];
    o[i] = v;
}

// ---------------- im2col (fp16) ----------------
__global__ void im2col_kernel(const float* __restrict__ x, __half* __restrict__ out)
{
    const int total = B_ * NPATCH_ * W_;
    int idx = blockIdx.x * 256 + threadIdx.x;
    if (idx >= total) return;
    const int kk = idx % W_;
    const int r  = idx / W_;
    const int b  = r / NPATCH_;
    const int p  = r % NPATCH_;
    const int ph = p / 14, pw = p % 14;
    const int c  = kk >> 8;
    const int py = (kk >> 4) & 15;
    const int px = kk & 15;
    out[idx] = __float2half(
        x[(((size_t)b * C_ + c) * IMG_ + ph * P_ + py) * IMG_ + pw * P_ + px]);
}

// ---------------- assemble ----------------
__global__ void assemble_kernel(const float* __restrict__ tok,
                                const float* __restrict__ cls,
                                const float* __restrict__ pe,
                                float* __restrict__ h)
{
    int idx = blockIdx.x * 256 + threadIdx.x;
    if (idx >= BSW_) return;
    const int w  = idx % W_;
    const int bs = idx / W_;
    const int s  = bs % S_;
    const int b  = bs / S_;
    float v = (s == 0) ? cls[w] : tok[((size_t)b * NPATCH_ + (s - 1)) * W_ + w];
    h[idx] = v + pe[(size_t)s * W_ + w];
}

// ---------------- layernorm: warp-per-row, float4, shuffle-only ----------------
__global__ void layernorm_kernel(const float* __restrict__ x,
                                 const float* __restrict__ gamma,
                                 const float* __restrict__ beta,
                                 __half* __restrict__ y, int nrows)
{
    const int warp = threadIdx.x >> 5, lane = threadIdx.x & 31;
    const int row = blockIdx.x * 8 + warp;
    if (row >= nrows) return;

    const float4* xr = reinterpret_cast<const float4*>(x + (size_t)row * W_);
    float4 v[6];
    float s = 0.f, s2 = 0.f;
    #pragma unroll
    for (int i = 0; i < 6; i++) {
        v[i] = xr[lane + 32 * i];
        s  += v[i].x + v[i].y + v[i].z + v[i].w;
        s2 += v[i].x * v[i].x + v[i].y * v[i].y + v[i].z * v[i].z + v[i].w * v[i].w;
    }
    #pragma unroll
    for (int off = 16; off > 0; off >>= 1) {
        s  += __shfl_xor_sync(0xffffffffu, s, off);
        s2 += __shfl_xor_sync(0xffffffffu, s2, off);
    }
    const float mean = s * (1.0f / W_);
    const float inv  = rsqrtf(s2 * (1.0f / W_) - mean * mean + 1e-5f);

    const float4* gp = reinterpret_cast<const float4*>(gamma);
    const float4* bp = reinterpret_cast<const float4*>(beta);
    uint2* yr = reinterpret_cast<uint2*>(y + (size_t)row * W_);
    #pragma unroll
    for (int i = 0; i < 6; i++) {
        const int c4 = lane + 32 * i;
        float4 g = gp[c4], bb = bp[c4];
        float o0 = (v[i].x - mean) * inv * g.x + bb.x;
        float o1 = (v[i].y - mean) * inv * g.y + bb.y;
        float o2 = (v[i].z - mean) * inv * g.z + bb.z;
        float o3 = (v[i].w - mean) * inv * g.w + bb.w;
        __half2 h0 = __floats2half2_rn(o0, o1);
        __half2 h1 = __floats2half2_rn(o2, o3);
        yr[c4] = make_uint2(*reinterpret_cast<uint32_t*>(&h0),
                            *reinterpret_cast<uint32_t*>(&h1));
    }
}

// ---------------- gather / l2norm ----------------
__global__ void gather_cls_kernel(const float* __restrict__ h, __half* __restrict__ cls)
{
    int idx = blockIdx.x * 256 + threadIdx.x;
    if (idx >= B_ * W_) return;
    const int b = idx / W_, w = idx % W_;
    cls[idx] = __float2half(h[(size_t)b * S_ * W_ + w]);
}

__global__ void l2norm_kernel(float* __restrict__ out)
{
    const int row = blockIdx.x;
    float* r = out + (size_t)row * E_;
    float s = 0.f;
    for (int i = threadIdx.x; i < E_; i += 256) { float v = r[i]; s += v * v; }
    for (int off = 16; off > 0; off >>= 1) s += __shfl_down_sync(0xffffffffu, s, off);
    __shared__ float rs[8];
    const int warp = threadIdx.x >> 5, lane = threadIdx.x & 31;
    if (lane == 0) rs[warp] = s;
    __syncthreads();
    __shared__ float inv_sh;
    if (threadIdx.x == 0) {
        float ts = 0.f;
        for (int i = 0; i < 8; i++) ts += rs[i];
        inv_sh = rsqrtf(ts);
    }
    __syncthreads();
    const float inv = inv_sh;
    for (int i = threadIdx.x; i < E_; i += 256) r[i] *= inv;
}

// ---------------- launch ----------------
extern "C" void kernel_launch(void* const* d_in, const int* in_sizes, int n_in,
                              void* d_out, int out_size)
{
    (void)in_sizes; (void)n_in; (void)out_size;

    const float* x       = (const float*)d_in[0];
    const float* conv_w  = (const float*)d_in[1];
    const float* conv_b  = (const float*)d_in[2];
    const float* cls_tok = (const float*)d_in[3];
    const float* pe      = (const float*)d_in[4];
    const float* ln1_g   = (const float*)d_in[5];
    const float* ln1_b   = (const float*)d_in[6];
    const float* wq      = (const float*)d_in[7];
    const float* bq      = (const float*)d_in[8];
    const float* wk      = (const float*)d_in[9];
    const float* bk      = (const float*)d_in[10];
    const float* wv      = (const float*)d_in[11];
    const float* bv      = (const float*)d_in[12];
    const float* wo      = (const float*)d_in[13];
    const float* bo      = (const float*)d_in[14];
    const float* ln2_g   = (const float*)d_in[15];
    const float* ln2_b   = (const float*)d_in[16];
    const float* w1      = (const float*)d_in[17];
    const float* b1      = (const float*)d_in[18];
    const float* w2      = (const float*)d_in[19];
    const float* b2      = (const float*)d_in[20];
    const float* proj    = (const float*)d_in[21];
    float* out           = (float*)d_out;

    float  *h, *tok, *bqkv;
    __half *y, *qh, *kh, *vh, *o, *ff, *i2c, *cls, *convw16;
    __half *wqkvT, *woT, *w1T, *w2T, *projT;
    cudaGetSymbolAddress((void**)&h,    g_h);
    cudaGetSymbolAddress((void**)&y,    g_y);
    cudaGetSymbolAddress((void**)&qh,   g_qh);
    cudaGetSymbolAddress((void**)&kh,   g_kh);
    cudaGetSymbolAddress((void**)&vh,   g_vh);
    cudaGetSymbolAddress((void**)&o,    g_o);
    cudaGetSymbolAddress((void**)&ff,   g_ff);
    cudaGetSymbolAddress((void**)&i2c,  g_im2col);
    cudaGetSymbolAddress((void**)&tok,  g_tok);
    cudaGetSymbolAddress((void**)&cls,  g_cls);
    cudaGetSymbolAddress((void**)&convw16, g_convw16);
    cudaGetSymbolAddress((void**)&wqkvT, g_wqkvT);
    cudaGetSymbolAddress((void**)&bqkv,  g_bqkv);
    cudaGetSymbolAddress((void**)&woT,  g_woT);
    cudaGetSymbolAddress((void**)&w1T,  g_w1T);
    cudaGetSymbolAddress((void**)&w2T,  g_w2T);
    cudaGetSymbolAddress((void**)&projT, g_projT);

    cudaFuncSetAttribute(gemm_wide<1,0,0,0>, cudaFuncAttributeMaxDynamicSharedMemorySize, WSMEM);
    cudaFuncSetAttribute(gemm_wide<1,0,0,3>, cudaFuncAttributeMaxDynamicSharedMemorySize, WSMEM);
    cudaFuncSetAttribute(gemm_wide<0,0,0,0>, cudaFuncAttributeMaxDynamicSharedMemorySize, WSMEM);
    cudaFuncSetAttribute(gemm_wide<1,0,1,1>, cudaFuncAttributeMaxDynamicSharedMemorySize, WSMEM);
    cudaFuncSetAttribute(gemm_n<1,1>, cudaFuncAttributeMaxDynamicSharedMemorySize, NSMEM);
    cudaFuncSetAttribute(attn_fused, cudaFuncAttributeMaxDynamicSharedMemorySize, ATT_SMEM);

    const int M  = B_ * S_;       // 6304
    const int Mp = B_ * NPATCH_;  // 6272
    dim3 blkT(32, 8);

    im2col_kernel<<<(Mp * W_ + 255) / 256, 256>>>(x, i2c);
    convw_h_kernel<<<(W_ * W_ + 255) / 256, 256>>>(conv_w, convw16);
    transpose_h_kernel<<<dim3(W_/32, W_/32, L_), blkT>>>(wq, wqkvT, W_, W_, (long long)QKV_*W_, 0);
    transpose_h_kernel<<<dim3(W_/32, W_/32, L_), blkT>>>(wk, wqkvT, W_, W_, (long long)QKV_*W_, W_);
    transpose_h_kernel<<<dim3(W_/32, W_/32, L_), blkT>>>(wv, wqkvT, W_, W_, (long long)QKV_*W_, 2*W_);
    bias_concat_kernel<<<(L_*QKV_ + 255) / 256, 256>>>(bq, bk, bv, bqkv);
    transpose_h_kernel<<<dim3(W_/32,  W_/32,  L_), blkT>>>(wo, woT, W_, W_, (long long)W_*W_, 0);
    transpose_h_kernel<<<dim3(FF_/32, W_/32,  L_), blkT>>>(w1, w1T, W_, FF_, (long long)W_*FF_, 0);
    transpose_h_kernel<<<dim3(W_/32,  FF_/32, L_), blkT>>>(w2, w2T, FF_, W_, (long long)FF_*W_, 0);
    transpose_h_kernel<<<dim3(E_/32,  W_/32,  1),  blkT>>>(proj, projT, W_, E_, (long long)W_*E_, 0);

    {   // patch embed GEMM -> tok (f32)
        dim3 grid(3, (Mp + 127) / 128, 1);
        gemm_wide<1,0,0,0><<<grid, 512, WSMEM>>>(i2c, convw16, conv_b, tok,
            nullptr, nullptr, nullptr, Mp, W_, W_, W_, W_, W_);
    }
    assemble_kernel<<<(BSW_ + 255) / 256, 256>>>(tok, cls_tok, pe, h);

    dim3 gridQKV(QKV_ / 256, (M + 127) / 128, 1);
    dim3 gridN  (W_ / 128, (M + 127) / 128, 1);     // narrow: (6, 50)
    dim3 gridFF (FF_ / 256, (M + 127) / 128, 1);
    dim3 gridAtt(2, B_ * H_, 1);
    const int lnGrid = (M + 7) / 8;

    for (int l = 0; l < L_; l++) {
        const size_t bOff = (size_t)l * W_;

        layernorm_kernel<<<lnGrid, 256>>>(h, ln1_g + bOff, ln1_b + bOff, y, M);
        gemm_wide<1,0,0,3><<<gridQKV, 512, WSMEM>>>(y, wqkvT + (size_t)l * QKV_ * W_,
            bqkv + (size_t)l * QKV_, nullptr, qh, kh, vh,
            M, QKV_, W_, W_, W_, 0);
        attn_fused<<<gridAtt, 256, ATT_SMEM>>>(qh, kh, vh, o);
        gemm_n<1,1><<<gridN, 256, NSMEM>>>(o, woT + (size_t)l * W_ * W_,
            bo + bOff, h, M, W_, W_, W_, W_, W_);
        layernorm_kernel<<<lnGrid, 256>>>(h, ln2_g + bOff, ln2_b + bOff, y, M);
        gemm_wide<1,0,1,1><<<gridFF, 512, WSMEM>>>(y, w1T + (size_t)l * W_ * FF_,
            b1 + (size_t)l * FF_, nullptr, ff, nullptr, nullptr,
            M, FF_, W_, W_, W_, FF_);
        gemm_n<1,1><<<gridN, 256, NSMEM>>>(ff, w2T + (size_t)l * FF_ * W_,
            b2 + bOff, h, M, W_, FF_, FF_, FF_, W_);
    }

    gather_cls_kernel<<<(B_ * W_ + 255) / 256, 256>>>(h, cls);
    {
        dim3 grid(2, 1, 1);
        gemm_wide<0,0,0,0><<<grid, 512, WSMEM>>>(cls, projT, nullptr, out,
            nullptr, nullptr, nullptr, B_, E_, W_, W_, W_, E_);
    }
    l2norm_kernel<<<B_, 256>>>(out);
}